// round 1
// baseline (speedup 1.0000x reference)
#include <cuda_runtime.h>
#include <cstdint>
#include <math.h>

// ---------------- problem constants ----------------
#define SIGMA_C 0.14f
#define L_C     1.0f
#define R0_C    50.0f
#define DT_C    0.1f
#define NT_C    2000
#define B_C     4096

// rho(j) lookup table: j in [0, 3.5] (j = 0.14*BC/(0.14*res+1), BC<=199.9, res>=50
// is an invariant => j <= 3.49825). 16384 segments, centered-slope form.
#define TABN   16384
#define NNODES (TABN + 2)   // nodes at x = (i-1)*h, i in [0, TABN+1]
#define JMAX_C 3.5f

__device__ float g_nodes[NNODES];

// ---------------------------------------------------------------------------
// Kernel 1: evaluate the exact fp32 MLP rho(x) at each table node.
// x_i = (i-1)*h. One thread per node. Layer-1 activations staged in SMEM so the
// j-loop can use dynamic indexing without local-memory spills.
// h1s layout [u][tid] => lanes read consecutive addresses (conflict-free).
// ---------------------------------------------------------------------------
__global__ void __launch_bounds__(128)
build_nodes_kernel(const float* __restrict__ W1, const float* __restrict__ b1,
                   const float* __restrict__ W2, const float* __restrict__ b2,
                   const float* __restrict__ W3, const float* __restrict__ b3) {
    __shared__ float h1s[64 * 128];
    const int tid = threadIdx.x;
    const int i = blockIdx.x * 128 + tid;

    const float H = JMAX_C / (float)TABN;
    const float x = (float)(i - 1) * H;

#pragma unroll
    for (int u = 0; u < 64; ++u)
        h1s[u * 128 + tid] = fmaxf(fmaf(x, __ldg(W1 + u), __ldg(b1 + u)), 0.0f);
    // each thread reads back only its own column -> no __syncthreads needed

    float out = __ldg(b3);
    for (int k0 = 0; k0 < 64; k0 += 16) {
        float acc[16];
#pragma unroll
        for (int kk = 0; kk < 16; ++kk) acc[kk] = __ldg(b2 + k0 + kk);
#pragma unroll 8
        for (int j = 0; j < 64; ++j) {
            const float hj = h1s[j * 128 + tid];
            const float4* row = reinterpret_cast<const float4*>(W2 + j * 64 + k0);
#pragma unroll
            for (int q = 0; q < 4; ++q) {
                float4 w = __ldg(row + q);
                acc[q * 4 + 0] = fmaf(hj, w.x, acc[q * 4 + 0]);
                acc[q * 4 + 1] = fmaf(hj, w.y, acc[q * 4 + 1]);
                acc[q * 4 + 2] = fmaf(hj, w.z, acc[q * 4 + 2]);
                acc[q * 4 + 3] = fmaf(hj, w.w, acc[q * 4 + 3]);
            }
        }
#pragma unroll
        for (int kk = 0; kk < 16; ++kk)
            out = fmaf(fmaxf(acc[kk], 0.0f), __ldg(W3 + k0 + kk), out);
    }

    if (i < NNODES) g_nodes[i] = out;
}

// ---------------------------------------------------------------------------
// Kernel 2: the 2000-step time loop. One thread per batch element,
// 128 CTAs x 32 threads (1 warp/SM -> latency-bound by the per-step RAW chain;
// keeps L1 write wavefronts off the critical path).
// rho via round-to-nearest magic-number index + centered-slope lerp (1 LDS.64).
// SCALE=1e9 sigmoids are exact selects in fp32.
// Outputs staged 16 steps in registers, written as float4s.
// ---------------------------------------------------------------------------
extern __shared__ float2 s_tab[];   // TABN entries, 128 KB

__global__ void __launch_bounds__(32, 1)
simulate_kernel(const float* __restrict__ Cv, const float* __restrict__ Kp,
                const float* __restrict__ jminp, float* __restrict__ out) {
    const int tid = threadIdx.x;
    const float INVH = (float)TABN / JMAX_C;
    const float MAGIC = 12582912.0f;   // 1.5 * 2^23

    // build (value, slope) table in shared from global nodes
    for (int k = tid; k < TABN; k += 32) {
        const float nm = g_nodes[k];
        const float nc = g_nodes[k + 1];
        const float np = g_nodes[k + 2];
        s_tab[k] = make_float2(nc, 0.5f * (np - nm));
    }
    __syncthreads();

    const int e = blockIdx.x * 32 + tid;
    const float cv  = __ldg(Cv + e);
    const float kk  = __ldg(Kp + e);
    const float jmn = __ldg(jminp + e);

    // Qmin: leading constant computed in double (matches the Python-scalar path
    // in the reference), then one fp32 pow for K^(4/3).
    const double beta_d = 0.14 * 1.0 / (0.14 * 50.0 + 1.0);
    const float CQ = (float)pow(81.0 / (128.0 * beta_d), 1.0 / 3.0);
    const float Qmin = CQ * powf(kk, 4.0f / 3.0f);

    float res = R0_C, thk = 0.0f, Q = 0.0f;
    const float cvdt = __fmul_rn(cv, DT_C);

    float* oth = out + (size_t)e * NT_C;
    float* ore = oth + (size_t)B_C * NT_C;
    float* ocu = ore + (size_t)B_C * NT_C;
    float* oti = ocu + (size_t)B_C * NT_C;

    float sth[16], sre[16], scu[16];

    for (int tile = 0; tile < NT_C / 16; ++tile) {
        const float tf0 = (float)(tile * 16);
#pragma unroll
        for (int s = 0; s < 16; ++s) {
            if (s == 0 && tile == 0) {
                // t = 0 initial outputs
                sth[0] = 0.0f; sre[0] = R0_C; scu[0] = 1e-3f;
            } else {
                // step i = t-1, BC = DT*(i+1) = DT*t  (t exact in fp32)
                const float tf  = tf0 + (float)s;
                const float BC  = __fmul_rn(DT_C, tf);
                const float num = __fmul_rn(SIGMA_C, BC);
                const float den = fmaf(SIGMA_C, res, L_C);
                const float j   = __fdividef(num, den);
                // explicit mul-then-add: bit-exact Q pre-crossing vs XLA
                const float Qn  = __fadd_rn(Q, __fmul_rn(j, DT_C));

                // table lookup: idx = round(j/h), frac in [-0.5, 0.5]
                const float m = fmaf(j, INVH, MAGIC);
                unsigned iu = __float_as_uint(m) & 0x3FFFFFu;
                iu = min(iu, (unsigned)(TABN - 1));
                const float ffl  = __fadd_rn(m, -MAGIC);
                const float frac = fmaf(j, INVH, -ffl);
                const float2 te  = s_tab[iu];
                const float rho  = fmaf(te.y, frac, te.x);

                const float jd  = __fadd_rn(j, -jmn);
                const float thc = fmaxf(fmaf(cvdt, jd, thk), 0.0f);
                const float p   = __fmul_rn(rho, jd);
                const float rc  = fmaxf(fmaf(p, cvdt, res), R0_C);
                const bool adv  = Qn > Qmin;     // saturated sigmoid == select
                thk = adv ? thc : thk;
                res = adv ? rc : res;
                Q = Qn;
                sth[s] = thk; sre[s] = res; scu[s] = j;
            }
        }
        // flush staged tile: per-lane contiguous float4s; sector pairs fully
        // covered by adjacent instructions -> merged in L2, DRAM traffic == data.
        const int base = tile * 16;
#pragma unroll
        for (int q = 0; q < 4; ++q) {
            *reinterpret_cast<float4*>(oth + base + 4 * q) =
                make_float4(sth[4 * q], sth[4 * q + 1], sth[4 * q + 2], sth[4 * q + 3]);
            *reinterpret_cast<float4*>(ore + base + 4 * q) =
                make_float4(sre[4 * q], sre[4 * q + 1], sre[4 * q + 2], sre[4 * q + 3]);
            *reinterpret_cast<float4*>(ocu + base + 4 * q) =
                make_float4(scu[4 * q], scu[4 * q + 1], scu[4 * q + 2], scu[4 * q + 3]);
            const float tb = tf0 + (float)(4 * q);
            *reinterpret_cast<float4*>(oti + base + 4 * q) =
                make_float4(__fmul_rn(DT_C, tb),
                            __fmul_rn(DT_C, tb + 1.0f),
                            __fmul_rn(DT_C, tb + 2.0f),
                            __fmul_rn(DT_C, tb + 3.0f));
        }
    }
}

// ---------------------------------------------------------------------------
// Inputs (metadata order): Cv, K, jmin, W1, b1, W2, b2, W3, b3
// Output: concat(thickness, resistance, current, time), each (B, NT) row-major.
// ---------------------------------------------------------------------------
extern "C" void kernel_launch(void* const* d_in, const int* in_sizes, int n_in,
                              void* d_out, int out_size) {
    const float* Cv = (const float*)d_in[0];
    const float* K  = (const float*)d_in[1];
    const float* jm = (const float*)d_in[2];
    const float* W1 = (const float*)d_in[3];
    const float* b1 = (const float*)d_in[4];
    const float* W2 = (const float*)d_in[5];
    const float* b2 = (const float*)d_in[6];
    const float* W3 = (const float*)d_in[7];
    const float* b3 = (const float*)d_in[8];
    float* out = (float*)d_out;

    build_nodes_kernel<<<(NNODES + 127) / 128, 128>>>(W1, b1, W2, b2, W3, b3);

    cudaFuncSetAttribute(simulate_kernel,
                         cudaFuncAttributeMaxDynamicSharedMemorySize,
                         TABN * sizeof(float2));
    simulate_kernel<<<B_C / 32, 32, TABN * sizeof(float2)>>>(Cv, K, jm, out);
}

// round 2
// speedup vs baseline: 1.3483x; 1.3483x over previous
#include <cuda_runtime.h>
#include <cstdint>
#include <math.h>

// ---------------- problem constants ----------------
#define SIGMA_C 0.14f
#define L_C     1.0f
#define R0_C    50.0f
#define DT_C    0.1f
#define NT_C    2000
#define B_C     4096

// rho(j) lookup table: j in [0, 3.5]; res >= 50 invariant => j <= 3.499
#define TABN   16384
#define NNODES (TABN + 2)   // nodes at x = (i-1)*h
#define JMAX_C 3.5f

__device__ float  g_nodes[NNODES];
__device__ float2 g_tab[TABN];     // (value at node k+1, centered slope)
__device__ float  g_Q[NT_C];       // frozen-phase Q prefix (monotone; 1e30 filler)

// ---------------------------------------------------------------------------
// Kernel 1: (a) exact fp32 MLP rho(x) at each table node; (b) frozen-phase Q
// prefix in exact reference fp32 order (mul then add), built by one thread of
// the extra block (early-exits once Q > 20 >> max Qmin=5.68; rest = 1e30).
// ---------------------------------------------------------------------------
__global__ void __launch_bounds__(128)
build_nodes_kernel(const float* __restrict__ W1, const float* __restrict__ b1,
                   const float* __restrict__ W2, const float* __restrict__ b2,
                   const float* __restrict__ W3, const float* __restrict__ b3) {
    const int tid = threadIdx.x;

    if (blockIdx.x == 129) {           // Q-prefix block
        __shared__ int s_tmax;
        if (tid == 0) {
            float Q = 0.0f;
            g_Q[0] = 0.0f;
            int t = 1;
            for (; t < NT_C; ++t) {
                // frozen res=50 -> den=8.0 exactly -> j = num * 0.125 (exact /8)
                const float num = __fmul_rn(SIGMA_C, __fmul_rn(DT_C, (float)t));
                const float j   = __fmul_rn(num, 0.125f);
                Q = __fadd_rn(Q, __fmul_rn(j, DT_C));
                g_Q[t] = Q;
                if (Q > 20.0f) { ++t; break; }
            }
            s_tmax = t;
        }
        __syncthreads();
        for (int t = s_tmax + tid; t < NT_C; t += 128) g_Q[t] = 1e30f;
        return;
    }

    __shared__ float h1s[64 * 128];
    const int i = blockIdx.x * 128 + tid;
    const float H = JMAX_C / (float)TABN;
    const float x = (float)(i - 1) * H;

#pragma unroll
    for (int u = 0; u < 64; ++u)
        h1s[u * 128 + tid] = fmaxf(fmaf(x, __ldg(W1 + u), __ldg(b1 + u)), 0.0f);
    // each thread reads back only its own column -> no __syncthreads needed

    float out = __ldg(b3);
    for (int k0 = 0; k0 < 64; k0 += 16) {
        float acc[16];
#pragma unroll
        for (int kk = 0; kk < 16; ++kk) acc[kk] = __ldg(b2 + k0 + kk);
#pragma unroll 8
        for (int j = 0; j < 64; ++j) {
            const float hj = h1s[j * 128 + tid];
            const float4* row = reinterpret_cast<const float4*>(W2 + j * 64 + k0);
#pragma unroll
            for (int q = 0; q < 4; ++q) {
                float4 w = __ldg(row + q);
                acc[q * 4 + 0] = fmaf(hj, w.x, acc[q * 4 + 0]);
                acc[q * 4 + 1] = fmaf(hj, w.y, acc[q * 4 + 1]);
                acc[q * 4 + 2] = fmaf(hj, w.z, acc[q * 4 + 2]);
                acc[q * 4 + 3] = fmaf(hj, w.w, acc[q * 4 + 3]);
            }
        }
#pragma unroll
        for (int kk = 0; kk < 16; ++kk)
            out = fmaf(fmaxf(acc[kk], 0.0f), __ldg(W3 + k0 + kk), out);
    }
    if (i < NNODES) g_nodes[i] = out;
}

// Kernel 1b: pack (value, centered slope) table
__global__ void __launch_bounds__(256)
build_tab_kernel() {
    const int k = blockIdx.x * 256 + threadIdx.x;
    if (k < TABN) {
        const float nm = g_nodes[k], nc = g_nodes[k + 1], np = g_nodes[k + 2];
        g_tab[k] = make_float2(nc, 0.5f * (np - nm));
    }
}

// ---------------------------------------------------------------------------
// Kernel 2: time loop. 1 thread/element, 1 warp/SM. Per-step chain reduced to
//   den(fma) -> Newton(2 fma) -> j(mul) -> slope-corr(2 fma) -> p(mul)
//   -> rc(fma) -> fmax  (~36 cyc)
// LDS prefetched 1 step ahead with predicted index; 1/den carried via
// extrapolated rcp.approx + on-chain Newton (exact 0.125 in frozen phase).
// Gate replaced by precomputed crossing step t* (binary search on g_Q).
// ---------------------------------------------------------------------------
extern __shared__ char smem_raw[];   // [ float2 tab[TABN] | float Q[NT_C] ]

__global__ void __launch_bounds__(32, 1)
simulate_kernel(const float* __restrict__ Cv, const float* __restrict__ Kp,
                const float* __restrict__ jminp, float* __restrict__ out) {
    const int tid = threadIdx.x;
    const float INVH  = (float)TABN / JMAX_C;
    const float MAGIC = 12582912.0f;    // 1.5 * 2^23

    float2* s_tab = reinterpret_cast<float2*>(smem_raw);
    float*  sQ    = reinterpret_cast<float*>(smem_raw + TABN * sizeof(float2));

    {   // cooperative smem fill (float4 copies)
        const float4* st4 = reinterpret_cast<const float4*>(g_tab);
        float4* dt4 = reinterpret_cast<float4*>(s_tab);
        for (int i = tid; i < TABN / 2; i += 32) dt4[i] = st4[i];
        const float4* sq4 = reinterpret_cast<const float4*>(g_Q);
        float4* dq4 = reinterpret_cast<float4*>(sQ);
        for (int i = tid; i < NT_C / 4; i += 32) dq4[i] = sq4[i];
    }
    __syncthreads();

    const int e = blockIdx.x * 32 + tid;
    const float cv  = __ldg(Cv + e);
    const float kk  = __ldg(Kp + e);
    const float jmn = __ldg(jminp + e);

    const double beta_d = 0.14 * 1.0 / (0.14 * 50.0 + 1.0);
    const float CQ = (float)pow(81.0 / (128.0 * beta_d), 1.0 / 3.0);
    const float Qmin = CQ * powf(kk, 4.0f / 3.0f);

    // t* = first t with Q_t > Qmin (Q monotone; sQ[0]=0 <= Qmin always)
    int lo = 0, hi = NT_C;
    while (hi - lo > 1) {
        const int mid = (lo + hi) >> 1;
        if (sQ[mid] <= Qmin) lo = mid; else hi = mid;
    }
    const int tstar = hi;                         // in [1, NT_C]
    const int tmin  = __reduce_min_sync(0xFFFFFFFFu, tstar);

    float res = R0_C, thk = 0.0f;
    const float cvdt = __fmul_rn(cv, DT_C);

    // pipeline registers (valid once slow mode starts)
    float den_prev = 8.0f, upred = 0.125f, j_prev = 0.0f;
    float pv_val = 0.0f, pv_slope = 0.0f, pv_idxf = 0.0f;
    float num_cur = 0.0f, cvde_cur = 0.0f;
    bool inited = false;

    float* oth = out + (size_t)e * NT_C;
    float* ore = oth + (size_t)B_C * NT_C;
    float* ocu = ore + (size_t)B_C * NT_C;
    float* oti = ocu + (size_t)B_C * NT_C;

    float sth[16], sre[16], scu[16];

    for (int tile = 0; tile < NT_C / 16; ++tile) {
        const int base = tile * 16;
        const float tf0 = (float)base;

        if (base + 15 < tmin) {
            // -------- fast tile: whole warp still frozen, closed form --------
#pragma unroll
            for (int s = 0; s < 16; ++s) {
                const int t = base + s;
                sth[s] = 0.0f;
                sre[s] = R0_C;
                scu[s] = (t == 0) ? 1e-3f
                    : __fmul_rn(__fmul_rn(SIGMA_C, __fmul_rn(DT_C, (float)t)), 0.125f);
            }
        } else {
            if (!inited) {
                inited = true;
                const int t0 = base;               // t0-1 < tmin: all lanes frozen
                den_prev = 8.0f;                   // den(t0-1) exactly
                upred = 0.125f;                    // rcp(extrap den)=rcp(8) exact
                j_prev = (t0 == 0) ? 0.0f
                    : __fmul_rn(__fmul_rn(SIGMA_C, __fmul_rn(DT_C, (float)(t0 - 1))), 0.125f);
                const float j0 = __fmul_rn(__fmul_rn(SIGMA_C,
                                    __fmul_rn(DT_C, (float)t0)), 0.125f);
                const float m0 = fmaf(j0, INVH, MAGIC);
                const unsigned iu0 = min(__float_as_uint(m0) & 0x3FFFFFu,
                                         (unsigned)(TABN - 1));
                pv_idxf = __fadd_rn(m0, -MAGIC);
                const float2 te0 = s_tab[iu0];
                pv_val = te0.x; pv_slope = te0.y;
                num_cur  = __fmul_rn(SIGMA_C, __fmul_rn(DT_C, (float)t0));
                cvde_cur = (t0 >= tstar) ? cvdt : 0.0f;
            }
#pragma unroll
            for (int s = 0; s < 16; ++s) {
                const int t = base + s;
                // ---------------- critical chain ----------------
                const float den = fmaf(SIGMA_C, res, L_C);
                const float nt1 = fmaf(-den, upred, 2.0f);       // Newton
                const float u   = __fmul_rn(upred, nt1);         // ~1/den, fp32-exact
                const float j   = __fmul_rn(num_cur, u);
                const float db  = fmaf(j, INVH, -pv_idxf);       // bins from node
                const float rho = fmaf(pv_slope, db, pv_val);
                const float jd  = __fadd_rn(j, -jmn);
                const float p   = __fmul_rn(rho, jd);
                const float rc  = fmaf(p, cvde_cur, res);        // frozen: +0 exact
                res = fmaxf(rc, R0_C);
                thk = fmaxf(fmaf(cvde_cur, jd, thk), 0.0f);
                // ---------------- off-chain: prep step t+1 ----------------
                const float dpred = fmaf(2.0f, den, -den_prev);
                den_prev = den;
                asm("rcp.approx.f32 %0, %1;" : "=f"(upred) : "f"(dpred));
                const float jpred = fmaxf(fmaf(2.0f, j, -j_prev), 0.0f);
                j_prev = j;
                const float m  = fmaf(jpred, INVH, MAGIC);
                const unsigned iu = min(__float_as_uint(m) & 0x3FFFFFu,
                                        (unsigned)(TABN - 1));
                pv_idxf = __fadd_rn(m, -MAGIC);
                const float2 te = s_tab[iu];                     // prefetch LDS
                pv_val = te.x; pv_slope = te.y;
                num_cur  = __fmul_rn(SIGMA_C, __fmul_rn(DT_C, (float)(t + 1)));
                cvde_cur = (t + 1 >= tstar) ? cvdt : 0.0f;
                // ---------------- outputs ----------------
                sth[s] = thk; sre[s] = res;
                scu[s] = (t == 0) ? 1e-3f : j;
            }
        }

        // flush staged tile as float4s (sector pairs fully covered -> L2 merge)
#pragma unroll
        for (int q = 0; q < 4; ++q) {
            *reinterpret_cast<float4*>(oth + base + 4 * q) =
                make_float4(sth[4 * q], sth[4 * q + 1], sth[4 * q + 2], sth[4 * q + 3]);
            *reinterpret_cast<float4*>(ore + base + 4 * q) =
                make_float4(sre[4 * q], sre[4 * q + 1], sre[4 * q + 2], sre[4 * q + 3]);
            *reinterpret_cast<float4*>(ocu + base + 4 * q) =
                make_float4(scu[4 * q], scu[4 * q + 1], scu[4 * q + 2], scu[4 * q + 3]);
            const float tb = tf0 + (float)(4 * q);
            *reinterpret_cast<float4*>(oti + base + 4 * q) =
                make_float4(__fmul_rn(DT_C, tb),
                            __fmul_rn(DT_C, tb + 1.0f),
                            __fmul_rn(DT_C, tb + 2.0f),
                            __fmul_rn(DT_C, tb + 3.0f));
        }
    }
}

// ---------------------------------------------------------------------------
// Inputs: Cv, K, jmin, W1, b1, W2, b2, W3, b3
// Output: concat(thickness, resistance, current, time), each (B, NT).
// ---------------------------------------------------------------------------
extern "C" void kernel_launch(void* const* d_in, const int* in_sizes, int n_in,
                              void* d_out, int out_size) {
    const float* Cv = (const float*)d_in[0];
    const float* K  = (const float*)d_in[1];
    const float* jm = (const float*)d_in[2];
    const float* W1 = (const float*)d_in[3];
    const float* b1 = (const float*)d_in[4];
    const float* W2 = (const float*)d_in[5];
    const float* b2 = (const float*)d_in[6];
    const float* W3 = (const float*)d_in[7];
    const float* b3 = (const float*)d_in[8];
    float* out = (float*)d_out;

    build_nodes_kernel<<<130, 128>>>(W1, b1, W2, b2, W3, b3);
    build_tab_kernel<<<TABN / 256, 256>>>();

    const int smem_bytes = TABN * sizeof(float2) + NT_C * sizeof(float);
    cudaFuncSetAttribute(simulate_kernel,
                         cudaFuncAttributeMaxDynamicSharedMemorySize, smem_bytes);
    simulate_kernel<<<B_C / 32, 32, smem_bytes>>>(Cv, K, jm, out);
}

// round 3
// speedup vs baseline: 1.6798x; 1.2459x over previous
#include <cuda_runtime.h>
#include <cstdint>
#include <math.h>

// ---------------- problem constants ----------------
#define SIGMA_C 0.14f
#define L_C     1.0f
#define R0_C    50.0f
#define DT_C    0.1f
#define NT_C    2000
#define B_C     4096

// rho(j) table: j in [0, 3.5]; res >= 50 invariant => j <= 3.499
#define TABN   8192
#define NNODES (TABN + 2)
#define JMAX_C 3.5f
#define INVH_F ((float)TABN / JMAX_C)

__device__ float  g_nodes[NNODES];
__device__ float2 g_tab[TABN];    // (c0_k, c1_k): rho(j) = fma(j, c1, c0) near node k
__device__ float  g_Q[NT_C];      // frozen-phase Q prefix (monotone; 1e30 filler)
__device__ float  g_num[NT_C];    // num(t) = 0.14f * (0.1f * t), exact reference order

// ---------------------------------------------------------------------------
// time array writer: out_time[e][t] = DT * t. Pure DRAM-bound, full grid.
// ---------------------------------------------------------------------------
__global__ void __launch_bounds__(256)
time_kernel(float* __restrict__ tout) {
    const int total4 = B_C * NT_C / 4;
    const int NT4 = NT_C / 4;
    for (int i4 = blockIdx.x * 256 + threadIdx.x; i4 < total4;
         i4 += gridDim.x * 256) {
        const int r = i4 % NT4;
        const float t0 = (float)(r * 4);
        reinterpret_cast<float4*>(tout)[i4] =
            make_float4(__fmul_rn(DT_C, t0),
                        __fmul_rn(DT_C, t0 + 1.0f),
                        __fmul_rn(DT_C, t0 + 2.0f),
                        __fmul_rn(DT_C, t0 + 3.0f));
    }
}

// ---------------------------------------------------------------------------
// build_nodes: exact fp32 MLP rho(x) at table nodes. 4 threads per node,
// 16 layer-2 units each, W2 cached in SMEM, h1 staged in SMEM.
// Block = 128 threads = 32 nodes. Last block (AUX_BLOCK) builds g_Q / g_num.
// ---------------------------------------------------------------------------
#define NODE_BLOCKS ((NNODES + 31) / 32)      // 257
#define AUX_BLOCK   NODE_BLOCKS               // one extra block

__global__ void __launch_bounds__(128)
build_nodes_kernel(const float* __restrict__ W1, const float* __restrict__ b1,
                   const float* __restrict__ W2, const float* __restrict__ b2,
                   const float* __restrict__ W3, const float* __restrict__ b3) {
    const int tid = threadIdx.x;

    if (blockIdx.x == AUX_BLOCK) {
        // ---- Q prefix + num table ----
        __shared__ float sj[NT_C];
        __shared__ int s_tmax;
        for (int t = tid; t < NT_C; t += 128) {
            // exact reference order: num = 0.14f * (0.1f * t); frozen j = num/8
            const float num = __fmul_rn(SIGMA_C, __fmul_rn(DT_C, (float)t));
            g_num[t] = num;
            sj[t] = __fmul_rn(__fmul_rn(num, 0.125f), DT_C);
        }
        __syncthreads();
        if (tid == 0) {
            float Q = 0.0f;
            g_Q[0] = 0.0f;
            int t = 1;
            for (; t < NT_C; ++t) {
                Q = __fadd_rn(Q, sj[t]);   // exact serial rounding
                g_Q[t] = Q;
                if (Q > 20.0f) { ++t; break; }   // 20 >> max Qmin (~5.7)
            }
            s_tmax = t;
        }
        __syncthreads();
        for (int t = s_tmax + tid; t < NT_C; t += 128) g_Q[t] = 1e30f;
        return;
    }

    __shared__ float sW2[64 * 64];      // 16 KB
    __shared__ float sh1[32][64];       // 8 KB

    // cooperative W2 load (float4)
    {
        const float4* src = reinterpret_cast<const float4*>(W2);
        float4* dst = reinterpret_cast<float4*>(sW2);
#pragma unroll
        for (int q = 0; q < 8; ++q) dst[tid + 128 * q] = __ldg(src + tid + 128 * q);
    }

    const int nl = tid >> 2;            // node within block (0..31)
    const int c  = tid & 3;             // unit chunk (0..3), 16 units each
    const int node = blockIdx.x * 32 + nl;

    const float H = JMAX_C / (float)TABN;
    const float x = (float)(node - 1) * H;

    // h1 for units c*16 .. c*16+15
#pragma unroll
    for (int k = 0; k < 16; ++k) {
        const int u = c * 16 + k;
        sh1[nl][u] = fmaxf(fmaf(x, __ldg(W1 + u), __ldg(b1 + u)), 0.0f);
    }
    __syncthreads();

    float acc[16];
#pragma unroll
    for (int k = 0; k < 16; ++k) acc[k] = __ldg(b2 + c * 16 + k);

#pragma unroll 4
    for (int j = 0; j < 64; ++j) {
        const float hj = sh1[nl][j];
        const float4* row = reinterpret_cast<const float4*>(sW2 + j * 64 + c * 16);
#pragma unroll
        for (int q = 0; q < 4; ++q) {
            const float4 w = row[q];
            acc[q * 4 + 0] = fmaf(hj, w.x, acc[q * 4 + 0]);
            acc[q * 4 + 1] = fmaf(hj, w.y, acc[q * 4 + 1]);
            acc[q * 4 + 2] = fmaf(hj, w.z, acc[q * 4 + 2]);
            acc[q * 4 + 3] = fmaf(hj, w.w, acc[q * 4 + 3]);
        }
    }

    float part = 0.0f;
#pragma unroll
    for (int k = 0; k < 16; ++k)
        part = fmaf(fmaxf(acc[k], 0.0f), __ldg(W3 + c * 16 + k), part);

    // reduce across the 4 chunk-lanes (quad-local)
    part += __shfl_down_sync(0xFFFFFFFFu, part, 2);
    part += __shfl_down_sync(0xFFFFFFFFu, part, 1);

    if (c == 0 && node < NNODES) g_nodes[node] = part + __ldg(b3);
}

// ---------------------------------------------------------------------------
// build_tab: pack per-node affine coeffs.
// rho(j) ~ val_k + slope_k*(j*INVH - k) = c0_k + c1_k * j
// ---------------------------------------------------------------------------
__global__ void __launch_bounds__(256)
build_tab_kernel() {
    const int k = blockIdx.x * 256 + threadIdx.x;
    if (k < TABN) {
        const float nm = g_nodes[k], nc = g_nodes[k + 1], np = g_nodes[k + 2];
        const float slope = 0.5f * (np - nm);               // per-bin slope
        const float c1 = slope * INVH_F;
        const float c0 = fmaf(-slope, (float)k, nc);
        g_tab[k] = make_float2(c0, c1);
    }
}

// ---------------------------------------------------------------------------
// simulate: 1 thread/element, 1 warp/SM. Per-step:
//   chain (fma): den -> Newton(2) -> j -> rho -> [jd] -> rc  (~28 cyc)
//   off-chain:   rcp.approx on extrapolated den, index predict + LDS.64
//                prefetch, num via SMEM, gate folded into (cvde, mjc).
// Outputs (thk,res,j) staged 16 steps, flushed as STG.128; time written
// by time_kernel.
// ---------------------------------------------------------------------------
extern __shared__ char smem_raw[];
// layout: float2 tab[TABN] | float Q[NT_C] | float num[NT_C + 4]

__global__ void __launch_bounds__(32, 1)
simulate_kernel(const float* __restrict__ Cv, const float* __restrict__ Kp,
                const float* __restrict__ jminp, float* __restrict__ out) {
    const int tid = threadIdx.x;
    const float MAGIC = 12582912.0f;    // 1.5 * 2^23

    float2* s_tab = reinterpret_cast<float2*>(smem_raw);
    float*  sQ    = reinterpret_cast<float*>(smem_raw + TABN * sizeof(float2));
    float*  s_num = sQ + NT_C;

    {   // cooperative smem fill
        const float4* st4 = reinterpret_cast<const float4*>(g_tab);
        float4* dt4 = reinterpret_cast<float4*>(s_tab);
        for (int i = tid; i < TABN / 2; i += 32) dt4[i] = st4[i];
        const float4* sq4 = reinterpret_cast<const float4*>(g_Q);
        float4* dq4 = reinterpret_cast<float4*>(sQ);
        for (int i = tid; i < NT_C / 4; i += 32) dq4[i] = sq4[i];
        const float4* sn4 = reinterpret_cast<const float4*>(g_num);
        float4* dn4 = reinterpret_cast<float4*>(s_num);
        for (int i = tid; i < NT_C / 4; i += 32) dn4[i] = sn4[i];
        if (tid == 0) {                        // pad (read at t=1999 prep, unused)
            s_num[NT_C] = s_num[NT_C - 1];
            s_num[NT_C + 1] = 0.0f; s_num[NT_C + 2] = 0.0f; s_num[NT_C + 3] = 0.0f;
        }
    }
    __syncthreads();

    const int e = blockIdx.x * 32 + tid;
    const float cv  = __ldg(Cv + e);
    const float kk  = __ldg(Kp + e);
    const float jmn = __ldg(jminp + e);

    const double beta_d = 0.14 * 1.0 / (0.14 * 50.0 + 1.0);
    const float CQ = (float)pow(81.0 / (128.0 * beta_d), 1.0 / 3.0);
    const float Qmin = CQ * powf(kk, 4.0f / 3.0f);

    // t* = first t with Q_t > Qmin (binary search, Q monotone)
    int lo = 0, hi = NT_C;
    while (hi - lo > 1) {
        const int mid = (lo + hi) >> 1;
        if (sQ[mid] <= Qmin) lo = mid; else hi = mid;
    }
    const int tstar = hi;
    const int tmin  = __reduce_min_sync(0xFFFFFFFFu, tstar);

    float res = R0_C, thk = 0.0f;
    const float cvdt = __fmul_rn(cv, DT_C);
    const float mjc0 = __fmul_rn(-jmn, cvdt);

    float den_prev = 8.0f, upred = 0.125f, j_prev = 0.0f;
    float pv_c0 = 0.0f, pv_c1 = 0.0f;
    float num_cur = 0.0f, cvde_cur = 0.0f, mjc_cur = 0.0f;
    bool inited = false;

    float* oth = out + (size_t)e * NT_C;
    float* ore = oth + (size_t)B_C * NT_C;
    float* ocu = ore + (size_t)B_C * NT_C;

    float sth[16], sre[16], scu[16];

    for (int tile = 0; tile < NT_C / 16; ++tile) {
        const int base = tile * 16;

        if (base + 15 < tmin) {
            // -------- frozen tile: closed form --------
#pragma unroll
            for (int s = 0; s < 16; ++s) {
                const int t = base + s;
                sth[s] = 0.0f;
                sre[s] = R0_C;
                scu[s] = (t == 0) ? 1e-3f : __fmul_rn(s_num[t], 0.125f);
            }
        } else {
            if (!inited) {
                inited = true;
                const int t0 = base;            // t0 <= tmin: all lanes frozen at t0-1
                den_prev = 8.0f;
                upred = 0.125f;
                j_prev = (t0 == 0) ? 0.0f : __fmul_rn(s_num[t0 - 1], 0.125f);
                const float j0 = __fmul_rn(s_num[t0], 0.125f);
                const float m0 = fmaf(j0, INVH_F, MAGIC);
                const unsigned iu0 = min(__float_as_uint(m0) & 0x3FFFFFu,
                                         (unsigned)(TABN - 1));
                const float2 te0 = s_tab[iu0];
                pv_c0 = te0.x; pv_c1 = te0.y;
                num_cur = s_num[t0];
                const bool adv0 = (t0 >= tstar);
                cvde_cur = adv0 ? cvdt : 0.0f;
                mjc_cur  = adv0 ? mjc0 : 0.0f;
            }
#pragma unroll
            for (int s = 0; s < 16; ++s) {
                const int t = base + s;
                // ---------------- critical chain ----------------
                const float den = fmaf(SIGMA_C, res, L_C);
                const float nt1 = fmaf(-den, upred, 2.0f);      // Newton
                const float u   = __fmul_rn(upred, nt1);
                const float j   = __fmul_rn(num_cur, u);
                const float rho = fmaf(j, pv_c1, pv_c0);
                const float jd  = fmaf(j, cvde_cur, mjc_cur);   // (j-jmin)*Cv*DT | 0
                const float rc  = fmaf(rho, jd, res);           // frozen: +0 exact
                res = fmaxf(rc, R0_C);
                thk = fmaxf(thk + jd, 0.0f);
                // ---------------- prep step t+1 (off-chain) ----------------
                const float dpred = fmaf(2.0f, den, -den_prev);
                den_prev = den;
                asm("rcp.approx.f32 %0, %1;" : "=f"(upred) : "f"(dpred));
                const float jpred = fmaf(2.0f, j, -j_prev);
                j_prev = j;
                const float m = fmaf(jpred, INVH_F, MAGIC);
                const unsigned iu = min(__float_as_uint(m) & 0x3FFFFFu,
                                        (unsigned)(TABN - 1));
                const float2 te = s_tab[iu];                    // LDS prefetch
                pv_c0 = te.x; pv_c1 = te.y;
                num_cur = s_num[t + 1];
                const bool adv = (t + 1 >= tstar);
                cvde_cur = adv ? cvdt : 0.0f;
                mjc_cur  = adv ? mjc0 : 0.0f;
                // ---------------- outputs ----------------
                sth[s] = thk; sre[s] = res; scu[s] = j;   // t>0 here (tmin >> 16)
            }
        }

        // flush staged tile (sector pairs fully covered -> L2 merge)
#pragma unroll
        for (int q = 0; q < 4; ++q) {
            *reinterpret_cast<float4*>(oth + base + 4 * q) =
                make_float4(sth[4 * q], sth[4 * q + 1], sth[4 * q + 2], sth[4 * q + 3]);
            *reinterpret_cast<float4*>(ore + base + 4 * q) =
                make_float4(sre[4 * q], sre[4 * q + 1], sre[4 * q + 2], sre[4 * q + 3]);
            *reinterpret_cast<float4*>(ocu + base + 4 * q) =
                make_float4(scu[4 * q], scu[4 * q + 1], scu[4 * q + 2], scu[4 * q + 3]);
        }
    }
}

// ---------------------------------------------------------------------------
// Inputs: Cv, K, jmin, W1, b1, W2, b2, W3, b3
// Output: concat(thickness, resistance, current, time), each (B, NT).
// ---------------------------------------------------------------------------
extern "C" void kernel_launch(void* const* d_in, const int* in_sizes, int n_in,
                              void* d_out, int out_size) {
    const float* Cv = (const float*)d_in[0];
    const float* K  = (const float*)d_in[1];
    const float* jm = (const float*)d_in[2];
    const float* W1 = (const float*)d_in[3];
    const float* b1 = (const float*)d_in[4];
    const float* W2 = (const float*)d_in[5];
    const float* b2 = (const float*)d_in[6];
    const float* W3 = (const float*)d_in[7];
    const float* b3 = (const float*)d_in[8];
    float* out = (float*)d_out;

    time_kernel<<<2048, 256>>>(out + (size_t)3 * B_C * NT_C);
    build_nodes_kernel<<<NODE_BLOCKS + 1, 128>>>(W1, b1, W2, b2, W3, b3);
    build_tab_kernel<<<(TABN + 255) / 256, 256>>>();

    const int smem_bytes = TABN * sizeof(float2) + (2 * NT_C + 4) * sizeof(float);
    cudaFuncSetAttribute(simulate_kernel,
                         cudaFuncAttributeMaxDynamicSharedMemorySize, smem_bytes);
    simulate_kernel<<<B_C / 32, 32, smem_bytes>>>(Cv, K, jm, out);
}

// round 4
// speedup vs baseline: 1.8625x; 1.1088x over previous
#include <cuda_runtime.h>
#include <cstdint>
#include <math.h>

// ---------------- problem constants ----------------
#define SIGMA_C 0.14f
#define L_C     1.0f
#define R0_C    50.0f
#define DT_C    0.1f
#define NT_C    2000
#define B_C     4096

// rho(j) table: j in [0, 3.5]; res >= 50 invariant => j <= 3.49825
#define TABN   4096
#define NNODES (TABN + 2)
#define JMAX_C 3.5f
#define INVH_F ((float)TABN / JMAX_C)

__device__ float  g_nodes[NNODES];
__device__ float2 g_tab[TABN];    // (c0_k, c1_k): rho(j) = fma(j, c1, c0) near node k
__device__ float  g_Q[NT_C];      // frozen-phase Q prefix (monotone; 1e30 filler)
__device__ float  g_num[NT_C + 4];// num(t) = 0.14f * (0.1f * t), exact ref order (+pad)

// ---------------------------------------------------------------------------
// time array writer: out_time[e][t] = DT * t. Pure DRAM-bound.
// ---------------------------------------------------------------------------
__global__ void __launch_bounds__(256)
time_kernel(float* __restrict__ tout) {
    const int total4 = B_C * NT_C / 4;
    const int NT4 = NT_C / 4;
    for (int i4 = blockIdx.x * 256 + threadIdx.x; i4 < total4;
         i4 += gridDim.x * 256) {
        const int r = i4 % NT4;
        const float t0 = (float)(r * 4);
        reinterpret_cast<float4*>(tout)[i4] =
            make_float4(__fmul_rn(DT_C, t0),
                        __fmul_rn(DT_C, t0 + 1.0f),
                        __fmul_rn(DT_C, t0 + 2.0f),
                        __fmul_rn(DT_C, t0 + 3.0f));
    }
}

// ---------------------------------------------------------------------------
// build_nodes: exact fp32 MLP rho(x) at table nodes. 4 threads/node, 16 units
// each, W2 in SMEM. Last block (AUX) builds g_Q / g_num.
// ---------------------------------------------------------------------------
#define NODE_BLOCKS ((NNODES + 31) / 32)      // 129
#define AUX_BLOCK   NODE_BLOCKS

__global__ void __launch_bounds__(128)
build_nodes_kernel(const float* __restrict__ W1, const float* __restrict__ b1,
                   const float* __restrict__ W2, const float* __restrict__ b2,
                   const float* __restrict__ W3, const float* __restrict__ b3) {
    const int tid = threadIdx.x;

    if (blockIdx.x == AUX_BLOCK) {
        __shared__ float sj[NT_C];
        __shared__ int s_tmax;
        for (int t = tid; t < NT_C; t += 128) {
            const float num = __fmul_rn(SIGMA_C, __fmul_rn(DT_C, (float)t));
            g_num[t] = num;
            sj[t] = __fmul_rn(__fmul_rn(num, 0.125f), DT_C);
        }
        if (tid == 0) {
            g_num[NT_C]     = g_num[NT_C - 1];
            g_num[NT_C + 1] = g_num[NT_C - 1];
            g_num[NT_C + 2] = 0.0f; g_num[NT_C + 3] = 0.0f;
        }
        __syncthreads();
        if (tid == 0) {
            float Q = 0.0f;
            g_Q[0] = 0.0f;
            int t = 1;
            for (; t < NT_C; ++t) {
                Q = __fadd_rn(Q, sj[t]);        // exact serial rounding
                g_Q[t] = Q;
                if (Q > 20.0f) { ++t; break; }  // 20 >> max Qmin (~5.7)
            }
            s_tmax = t;
        }
        __syncthreads();
        for (int t = s_tmax + tid; t < NT_C; t += 128) g_Q[t] = 1e30f;
        return;
    }

    __shared__ float sW2[64 * 64];
    __shared__ float sh1[32][64];
    {
        const float4* src = reinterpret_cast<const float4*>(W2);
        float4* dst = reinterpret_cast<float4*>(sW2);
#pragma unroll
        for (int q = 0; q < 8; ++q) dst[tid + 128 * q] = __ldg(src + tid + 128 * q);
    }

    const int nl = tid >> 2;
    const int c  = tid & 3;
    const int node = blockIdx.x * 32 + nl;
    const float H = JMAX_C / (float)TABN;
    const float x = (float)(node - 1) * H;

#pragma unroll
    for (int k = 0; k < 16; ++k) {
        const int u = c * 16 + k;
        sh1[nl][u] = fmaxf(fmaf(x, __ldg(W1 + u), __ldg(b1 + u)), 0.0f);
    }
    __syncthreads();

    float acc[16];
#pragma unroll
    for (int k = 0; k < 16; ++k) acc[k] = __ldg(b2 + c * 16 + k);
#pragma unroll 4
    for (int j = 0; j < 64; ++j) {
        const float hj = sh1[nl][j];
        const float4* row = reinterpret_cast<const float4*>(sW2 + j * 64 + c * 16);
#pragma unroll
        for (int q = 0; q < 4; ++q) {
            const float4 w = row[q];
            acc[q * 4 + 0] = fmaf(hj, w.x, acc[q * 4 + 0]);
            acc[q * 4 + 1] = fmaf(hj, w.y, acc[q * 4 + 1]);
            acc[q * 4 + 2] = fmaf(hj, w.z, acc[q * 4 + 2]);
            acc[q * 4 + 3] = fmaf(hj, w.w, acc[q * 4 + 3]);
        }
    }
    float part = 0.0f;
#pragma unroll
    for (int k = 0; k < 16; ++k)
        part = fmaf(fmaxf(acc[k], 0.0f), __ldg(W3 + c * 16 + k), part);
    part += __shfl_down_sync(0xFFFFFFFFu, part, 2);
    part += __shfl_down_sync(0xFFFFFFFFu, part, 1);
    if (c == 0 && node < NNODES) g_nodes[node] = part + __ldg(b3);
}

__global__ void __launch_bounds__(256)
build_tab_kernel() {
    const int k = blockIdx.x * 256 + threadIdx.x;
    if (k < TABN) {
        const float nm = g_nodes[k], nc = g_nodes[k + 1], np = g_nodes[k + 2];
        const float slope = 0.5f * (np - nm);
        const float c1 = slope * INVH_F;
        const float c0 = fmaf(-slope, (float)k, nc);
        g_tab[k] = make_float2(c0, c1);
    }
}

// ---------------------------------------------------------------------------
// simulate: 1 thread/element. Loop-carried chain reduced to 5 ops (~21 cyc):
//   nt1 = fma(res,su,lu); j = nu*nt1; t1 = fma(j,A,B); rc = fma(t1,j,res+C);
//   res = fmnmx(rc, 50)
// All slow producers (rcp.approx, table LDS) pipelined TWO steps ahead via
// linear extrapolation of den and j; Newton (folded into su/lu) and the
// affine segment extension absorb the prediction error quadratically.
// Frozen phase (t < tstar) is bit-exact with the reference.
// ---------------------------------------------------------------------------
extern __shared__ char smem_raw[];
// layout: float2 tab[TABN] | float Q[NT_C] | float num[NT_C + 4]

__global__ void __launch_bounds__(32, 1)
simulate_kernel(const float* __restrict__ Cv, const float* __restrict__ Kp,
                const float* __restrict__ jminp, float* __restrict__ out) {
    const int tid = threadIdx.x;
    const float MAGIC = 12582912.0f;    // 1.5 * 2^23

    float2* s_tab = reinterpret_cast<float2*>(smem_raw);
    float*  sQ    = reinterpret_cast<float*>(smem_raw + TABN * sizeof(float2));
    float*  s_num = sQ + NT_C;

    {
        const float4* st4 = reinterpret_cast<const float4*>(g_tab);
        float4* dt4 = reinterpret_cast<float4*>(s_tab);
        for (int i = tid; i < TABN / 2; i += 32) dt4[i] = st4[i];
        const float4* sq4 = reinterpret_cast<const float4*>(g_Q);
        float4* dq4 = reinterpret_cast<float4*>(sQ);
        for (int i = tid; i < NT_C / 4; i += 32) dq4[i] = sq4[i];
        const float4* sn4 = reinterpret_cast<const float4*>(g_num);
        float4* dn4 = reinterpret_cast<float4*>(s_num);
        for (int i = tid; i < (NT_C + 4) / 4; i += 32) dn4[i] = sn4[i];
    }
    __syncthreads();

    const int e = blockIdx.x * 32 + tid;
    const float cv  = __ldg(Cv + e);
    const float kk  = __ldg(Kp + e);
    const float jmn = __ldg(jminp + e);

    const double beta_d = 0.14 * 1.0 / (0.14 * 50.0 + 1.0);
    const float CQ = (float)pow(81.0 / (128.0 * beta_d), 1.0 / 3.0);
    const float Qmin = CQ * powf(kk, 4.0f / 3.0f);

    // t* = first t with Q_t > Qmin (binary search; Q monotone; tstar >= ~120)
    int lo = 0, hi = NT_C;
    while (hi - lo > 1) {
        const int mid = (lo + hi) >> 1;
        if (sQ[mid] <= Qmin) lo = mid; else hi = mid;
    }
    const int tstar = hi;
    const int tmin  = __reduce_min_sync(0xFFFFFFFFu, tstar);

    float res = R0_C, thk = 0.0f;
    const float cvdt = __fmul_rn(cv, DT_C);
    const float mjc0c = __fmul_rn(-jmn, cvdt);

    // 2-deep pipeline state (cur = step t, nxt = step t+1)
    float su0, su1, lu0, lu1, nu0, nu1;
    float A0, A1, B0, B1, C0, C1;
    float cvde0, cvde1, mjc0, mjc1;
    float den_prev = 8.0f, j_prev = 0.0f;
    bool inited = false;

    float* oth = out + (size_t)e * NT_C;
    float* ore = oth + (size_t)B_C * NT_C;
    float* ocu = ore + (size_t)B_C * NT_C;

    float sth[16], sre[16], scu[16];

    for (int tile = 0; tile < NT_C / 16; ++tile) {
        const int base = tile * 16;

        if (base + 15 < tmin) {
            // -------- frozen tile: closed form (bit-exact) --------
#pragma unroll
            for (int s = 0; s < 16; ++s) {
                const int t = base + s;
                sth[s] = 0.0f;
                sre[s] = R0_C;
                scu[s] = (t == 0) ? 1e-3f : __fmul_rn(s_num[t], 0.125f);
            }
        } else {
            if (!inited) {
                inited = true;
                const int t0 = base;   // t0 <= tmin: res/den frozen through t0-1
                den_prev = 8.0f;                                   // den_{t0-1}
                j_prev   = __fmul_rn(s_num[t0 - 1], 0.125f);       // j_{t0-1}
                const float up = 0.125f;                           // exact
                su0 = su1 = __fmul_rn(up, -SIGMA_C);
                lu0 = lu1 = fmaf(up, -L_C, 2.0f);
                nu0 = __fmul_rn(s_num[t0],     up);
                nu1 = __fmul_rn(s_num[t0 + 1], up);
#pragma unroll
                for (int k = 0; k < 2; ++k) {
                    const float jk = (k == 0) ? nu0 : nu1;  // frozen j = num/8
                    const float m  = fmaf(jk, INVH_F, MAGIC);
                    const unsigned iu = min(__float_as_uint(m) & 0x3FFFFFu,
                                            (unsigned)(TABN - 1));
                    const float2 te = s_tab[iu];
                    const bool adv = (t0 + k >= tstar);
                    const float cd = adv ? cvdt  : 0.0f;
                    const float mj = adv ? mjc0c : 0.0f;
                    const float Ak = __fmul_rn(te.y, cd);
                    const float Bk = fmaf(te.y, mj, __fmul_rn(te.x, cd));
                    const float Ck = __fmul_rn(te.x, mj);
                    if (k == 0) { A0 = Ak; B0 = Bk; C0 = Ck; cvde0 = cd; mjc0 = mj; }
                    else        { A1 = Ak; B1 = Bk; C1 = Ck; cvde1 = cd; mjc1 = mj; }
                }
            }
#pragma unroll
            for (int s = 0; s < 16; ++s) {
                const int t = base + s;
                const float resin = res;
                // ---------------- critical chain (5 ops) ----------------
                const float nt1 = fmaf(resin, su0, lu0);     // Newton folded in
                const float jv  = __fmul_rn(nu0, nt1);
                const float t1  = fmaf(jv, A0, B0);
                const float rc  = fmaf(t1, jv, __fadd_rn(resin, C0));
                res = fmaxf(rc, R0_C);
                // ---------------- side outputs ----------------
                const float jd = fmaf(jv, cvde0, mjc0);      // frozen: exactly 0
                thk = __fadd_rn(thk, jd);                    // jd>0 post-cross
                sth[s] = thk; sre[s] = res; scu[s] = jv;
                // ---------------- prep step t+2 (off-chain) ----------------
                const float den = fmaf(SIGMA_C, resin, L_C);           // den_t
                const float dd  = fmaf(2.0f, __fadd_rn(den, -den_prev), den);
                den_prev = den;
                float up2;
                asm("rcp.approx.f32 %0, %1;" : "=f"(up2) : "f"(dd));
                const float su2 = __fmul_rn(up2, -SIGMA_C);
                const float lu2 = fmaf(up2, -L_C, 2.0f);
                const float nu2 = __fmul_rn(s_num[t + 2], up2);
                const float jp  = fmaf(2.0f, __fadd_rn(jv, -j_prev), jv);
                j_prev = jv;
                const float m = fmaf(jp, INVH_F, MAGIC);
                const unsigned iu = min(__float_as_uint(m) & 0x3FFFFFu,
                                        (unsigned)(TABN - 1));
                const float2 te = s_tab[iu];                 // LDS, 2 steps early
                const bool adv = (t + 2 >= tstar);
                const float cd2 = adv ? cvdt  : 0.0f;
                const float mj2 = adv ? mjc0c : 0.0f;
                const float A2 = __fmul_rn(te.y, cd2);
                const float B2 = fmaf(te.y, mj2, __fmul_rn(te.x, cd2));
                const float C2 = __fmul_rn(te.x, mj2);
                // rotate pipeline (renamed away by unroll)
                su0 = su1; su1 = su2;  lu0 = lu1; lu1 = lu2;
                nu0 = nu1; nu1 = nu2;
                A0 = A1; A1 = A2;  B0 = B1; B1 = B2;  C0 = C1; C1 = C2;
                cvde0 = cvde1; cvde1 = cd2;  mjc0 = mjc1; mjc1 = mj2;
            }
        }

        // flush staged tile (STG.128; sector pairs fully covered -> L2 merge)
#pragma unroll
        for (int q = 0; q < 4; ++q) {
            *reinterpret_cast<float4*>(oth + base + 4 * q) =
                make_float4(sth[4 * q], sth[4 * q + 1], sth[4 * q + 2], sth[4 * q + 3]);
            *reinterpret_cast<float4*>(ore + base + 4 * q) =
                make_float4(sre[4 * q], sre[4 * q + 1], sre[4 * q + 2], sre[4 * q + 3]);
            *reinterpret_cast<float4*>(ocu + base + 4 * q) =
                make_float4(scu[4 * q], scu[4 * q + 1], scu[4 * q + 2], scu[4 * q + 3]);
        }
    }
}

// ---------------------------------------------------------------------------
// Inputs: Cv, K, jmin, W1, b1, W2, b2, W3, b3
// Output: concat(thickness, resistance, current, time), each (B, NT).
// ---------------------------------------------------------------------------
extern "C" void kernel_launch(void* const* d_in, const int* in_sizes, int n_in,
                              void* d_out, int out_size) {
    const float* Cv = (const float*)d_in[0];
    const float* K  = (const float*)d_in[1];
    const float* jm = (const float*)d_in[2];
    const float* W1 = (const float*)d_in[3];
    const float* b1 = (const float*)d_in[4];
    const float* W2 = (const float*)d_in[5];
    const float* b2 = (const float*)d_in[6];
    const float* W3 = (const float*)d_in[7];
    const float* b3 = (const float*)d_in[8];
    float* out = (float*)d_out;

    time_kernel<<<2048, 256>>>(out + (size_t)3 * B_C * NT_C);
    build_nodes_kernel<<<NODE_BLOCKS + 1, 128>>>(W1, b1, W2, b2, W3, b3);
    build_tab_kernel<<<(TABN + 255) / 256, 256>>>();

    const int smem_bytes = TABN * sizeof(float2) + (2 * NT_C + 4) * sizeof(float);
    cudaFuncSetAttribute(simulate_kernel,
                         cudaFuncAttributeMaxDynamicSharedMemorySize, smem_bytes);
    simulate_kernel<<<B_C / 32, 32, smem_bytes>>>(Cv, K, jm, out);
}

// round 5
// speedup vs baseline: 2.1802x; 1.1705x over previous
#include <cuda_runtime.h>
#include <cstdint>
#include <math.h>

// ---------------- problem constants ----------------
#define SIGMA_C 0.14f
#define L_C     1.0f
#define R0_C    50.0f
#define DT_C    0.1f
#define NT_C    2000
#define B_C     4096

// rho(j) table: j in [0, 3.5]; res >= 50 invariant => j <= 3.49825
#define TABN   4096
#define NNODES (TABN + 2)
#define JMAX_C 3.5f
#define INVH_F ((float)TABN / JMAX_C)

__device__ float  g_nodes[NNODES];
__device__ float2 g_tab[TABN];    // (c0_k, c1_k): rho(j) = fma(j, c1, c0) near node k
__device__ float  g_Q[NT_C];      // frozen-phase Q prefix (monotone; 1e30 filler)

// ---------------------------------------------------------------------------
// time array writer: out_time[e][t] = DT * t. Pure DRAM-bound.
// ---------------------------------------------------------------------------
__global__ void __launch_bounds__(256)
time_kernel(float* __restrict__ tout) {
    const int total4 = B_C * NT_C / 4;
    const int NT4 = NT_C / 4;
    for (int i4 = blockIdx.x * 256 + threadIdx.x; i4 < total4;
         i4 += gridDim.x * 256) {
        const int r = i4 % NT4;
        const float t0 = (float)(r * 4);
        reinterpret_cast<float4*>(tout)[i4] =
            make_float4(__fmul_rn(DT_C, t0),
                        __fmul_rn(DT_C, t0 + 1.0f),
                        __fmul_rn(DT_C, t0 + 2.0f),
                        __fmul_rn(DT_C, t0 + 3.0f));
    }
}

// exact reference num(t) = 0.14f * (0.1f * t)
__device__ __forceinline__ float num_of(float tf) {
    return __fmul_rn(SIGMA_C, __fmul_rn(DT_C, tf));
}

// ---------------------------------------------------------------------------
// build_nodes: exact fp32 MLP rho(x) at table nodes. 4 threads/node, 16 units
// each, W2 in SMEM. Last block (AUX) builds g_Q.
// ---------------------------------------------------------------------------
#define NODE_BLOCKS ((NNODES + 31) / 32)      // 129
#define AUX_BLOCK   NODE_BLOCKS

__global__ void __launch_bounds__(128)
build_nodes_kernel(const float* __restrict__ W1, const float* __restrict__ b1,
                   const float* __restrict__ W2, const float* __restrict__ b2,
                   const float* __restrict__ W3, const float* __restrict__ b3) {
    const int tid = threadIdx.x;

    if (blockIdx.x == AUX_BLOCK) {
        __shared__ float sj[NT_C];
        __shared__ int s_tmax;
        for (int t = tid; t < NT_C; t += 128)
            sj[t] = __fmul_rn(__fmul_rn(num_of((float)t), 0.125f), DT_C);
        __syncthreads();
        if (tid == 0) {
            float Q = 0.0f;
            g_Q[0] = 0.0f;
            int t = 1;
            for (; t < NT_C; ++t) {
                Q = __fadd_rn(Q, sj[t]);        // exact serial rounding
                g_Q[t] = Q;
                if (Q > 20.0f) { ++t; break; }  // 20 >> max Qmin (~5.7)
            }
            s_tmax = t;
        }
        __syncthreads();
        for (int t = s_tmax + tid; t < NT_C; t += 128) g_Q[t] = 1e30f;
        return;
    }

    __shared__ float sW2[64 * 64];
    __shared__ float sh1[32][64];
    {
        const float4* src = reinterpret_cast<const float4*>(W2);
        float4* dst = reinterpret_cast<float4*>(sW2);
#pragma unroll
        for (int q = 0; q < 8; ++q) dst[tid + 128 * q] = __ldg(src + tid + 128 * q);
    }

    const int nl = tid >> 2;
    const int c  = tid & 3;
    const int node = blockIdx.x * 32 + nl;
    const float H = JMAX_C / (float)TABN;
    const float x = (float)(node - 1) * H;

#pragma unroll
    for (int k = 0; k < 16; ++k) {
        const int u = c * 16 + k;
        sh1[nl][u] = fmaxf(fmaf(x, __ldg(W1 + u), __ldg(b1 + u)), 0.0f);
    }
    __syncthreads();

    float acc[16];
#pragma unroll
    for (int k = 0; k < 16; ++k) acc[k] = __ldg(b2 + c * 16 + k);
#pragma unroll 4
    for (int j = 0; j < 64; ++j) {
        const float hj = sh1[nl][j];
        const float4* row = reinterpret_cast<const float4*>(sW2 + j * 64 + c * 16);
#pragma unroll
        for (int q = 0; q < 4; ++q) {
            const float4 w = row[q];
            acc[q * 4 + 0] = fmaf(hj, w.x, acc[q * 4 + 0]);
            acc[q * 4 + 1] = fmaf(hj, w.y, acc[q * 4 + 1]);
            acc[q * 4 + 2] = fmaf(hj, w.z, acc[q * 4 + 2]);
            acc[q * 4 + 3] = fmaf(hj, w.w, acc[q * 4 + 3]);
        }
    }
    float part = 0.0f;
#pragma unroll
    for (int k = 0; k < 16; ++k)
        part = fmaf(fmaxf(acc[k], 0.0f), __ldg(W3 + c * 16 + k), part);
    part += __shfl_down_sync(0xFFFFFFFFu, part, 2);
    part += __shfl_down_sync(0xFFFFFFFFu, part, 1);
    if (c == 0 && node < NNODES) g_nodes[node] = part + __ldg(b3);
}

__global__ void __launch_bounds__(256)
build_tab_kernel() {
    const int k = blockIdx.x * 256 + threadIdx.x;
    if (k < TABN) {
        const float nm = g_nodes[k], nc = g_nodes[k + 1], np = g_nodes[k + 2];
        const float slope = 0.5f * (np - nm);
        const float c1 = slope * INVH_F;
        const float c0 = fmaf(-slope, (float)k, nc);
        g_tab[k] = make_float2(c0, c1);
    }
}

// ---------------------------------------------------------------------------
// simulate: 1 thread/element. 5-op loop-carried chain:
//   nt1=fma(res,su,lu); j=nu*nt1; rho=fma(j,c1,c0) || jd=fma(j,cvde,mjc);
//   rc=fma(rho,jd,res); res=fmnmx(rc,50)
// Slow producers truly 2-stage pipelined:
//   iter t   : issue rcp.approx(extrap den) + table LDS for step t+2 (RAW regs)
//   iter t+1 : convert raw up -> su/lu/nu for step t+2 (MUFU had a full iter)
//   iter t+2 : consume; table entry used unconverted (c0,c1)
// num(t) inline from an exact float counter (no LDS). Frozen phase exact.
// ---------------------------------------------------------------------------
extern __shared__ char smem_raw[];
// layout: float2 tab[TABN] | float Q[NT_C]

__global__ void __launch_bounds__(32, 1)
simulate_kernel(const float* __restrict__ Cv, const float* __restrict__ Kp,
                const float* __restrict__ jminp, float* __restrict__ out) {
    const int tid = threadIdx.x;
    const float MAGIC = 12582912.0f;    // 1.5 * 2^23

    float2* s_tab = reinterpret_cast<float2*>(smem_raw);
    float*  sQ    = reinterpret_cast<float*>(smem_raw + TABN * sizeof(float2));
    {
        const float4* st4 = reinterpret_cast<const float4*>(g_tab);
        float4* dt4 = reinterpret_cast<float4*>(s_tab);
        for (int i = tid; i < TABN / 2; i += 32) dt4[i] = st4[i];
        const float4* sq4 = reinterpret_cast<const float4*>(g_Q);
        float4* dq4 = reinterpret_cast<float4*>(sQ);
        for (int i = tid; i < NT_C / 4; i += 32) dq4[i] = sq4[i];
    }
    __syncthreads();

    const int e = blockIdx.x * 32 + tid;
    const float cv  = __ldg(Cv + e);
    const float kk  = __ldg(Kp + e);
    const float jmn = __ldg(jminp + e);

    const double beta_d = 0.14 * 1.0 / (0.14 * 50.0 + 1.0);
    const float CQ = (float)pow(81.0 / (128.0 * beta_d), 1.0 / 3.0);
    const float Qmin = CQ * powf(kk, 4.0f / 3.0f);

    // t* = first t with Q_t > Qmin (binary search; Q monotone; tstar >= ~120)
    int lo = 0, hi = NT_C;
    while (hi - lo > 1) {
        const int mid = (lo + hi) >> 1;
        if (sQ[mid] <= Qmin) lo = mid; else hi = mid;
    }
    const int tstar = hi;
    const int tmin  = __reduce_min_sync(0xFFFFFFFFu, tstar);

    float res = R0_C, thk = 0.0f;
    const float cvdt = __fmul_rn(cv, DT_C);
    const float mjc0c = __fmul_rn(-jmn, cvdt);

    // stage-0 (consumed this iter) / raw pipe (issued 2 iters early)
    float su0, lu0, nu0, c0_0, c1_0, cvde0, mjc0;      // for step t
    float su1, lu1, nu1, cvde1, mjc1;                  // for step t+1 (converted)
    float2 te1;                                        // table for step t+1 (raw)
    float  up_raw;                                     // rcp result for step t+2
    float2 te_raw;                                     // table for step t+2
    float den_prev = 8.0f, j_prev = 0.0f;
    bool inited = false;

    float* oth = out + (size_t)e * NT_C;
    float* ore = oth + (size_t)B_C * NT_C;
    float* ocu = ore + (size_t)B_C * NT_C;

    float sth[4], sre[4], scu[4];

    for (int tile = 0; tile < NT_C / 16; ++tile) {
        const int base = tile * 16;
        const float tfb = (float)base;

        if (base + 15 < tmin) {
            // -------- frozen tile: closed form (bit-exact) --------
#pragma unroll
            for (int s = 0; s < 16; ++s) {
                const int t = base + s;
                sth[s & 3] = 0.0f;
                sre[s & 3] = R0_C;
                scu[s & 3] = (t == 0) ? 1e-3f
                           : __fmul_rn(num_of(tfb + (float)s), 0.125f);
                if ((s & 3) == 3) {
                    const int b4 = base + (s & ~3);
                    *reinterpret_cast<float4*>(oth + b4) =
                        make_float4(sth[0], sth[1], sth[2], sth[3]);
                    *reinterpret_cast<float4*>(ore + b4) =
                        make_float4(sre[0], sre[1], sre[2], sre[3]);
                    *reinterpret_cast<float4*>(ocu + b4) =
                        make_float4(scu[0], scu[1], scu[2], scu[3]);
                }
            }
        } else {
            if (!inited) {
                inited = true;
                const int t0 = base;     // t0 <= tmin: res frozen (=50) entering t0
                den_prev = 8.0f;                                    // den_{t0-1}
                j_prev   = __fmul_rn(num_of(tfb - 1.0f), 0.125f);   // j_{t0-1}
                const float up = 0.125f;                            // exact
                // stage for t0
                su0 = __fmul_rn(up, -SIGMA_C);
                lu0 = fmaf(up, -L_C, 2.0f);
                nu0 = __fmul_rn(num_of(tfb), up);
                // stage for t0+1
                su1 = su0; lu1 = lu0;
                nu1 = __fmul_rn(num_of(tfb + 1.0f), up);
                up_raw = up;                                        // for t0+2
#pragma unroll
                for (int k = 0; k < 3; ++k) {       // tables for t0, t0+1, t0+2
                    const float jk = __fmul_rn(num_of(tfb + (float)k), 0.125f);
                    const float m  = fmaf(jk, INVH_F, MAGIC);
                    const unsigned iu = min(__float_as_uint(m) & 0x3FFFFFu,
                                            (unsigned)(TABN - 1));
                    const float2 te = s_tab[iu];
                    if (k == 0) { c0_0 = te.x; c1_0 = te.y; }
                    else if (k == 1) te1 = te;
                    else te_raw = te;
                }
                const bool a0 = (t0 >= tstar);
                cvde0 = a0 ? cvdt : 0.0f;  mjc0 = a0 ? mjc0c : 0.0f;
                const bool a1 = (t0 + 1 >= tstar);
                cvde1 = a1 ? cvdt : 0.0f;  mjc1 = a1 ? mjc0c : 0.0f;
            }
#pragma unroll
            for (int s = 0; s < 16; ++s) {
                const int t = base + s;
                const float resin = res;
                // ---------------- critical chain (5 ops) ----------------
                const float nt1 = fmaf(resin, su0, lu0);      // Newton folded in
                const float jv  = __fmul_rn(nu0, nt1);
                const float rho = fmaf(jv, c1_0, c0_0);
                const float jd  = fmaf(jv, cvde0, mjc0);      // frozen: exactly 0
                const float rc  = fmaf(rho, jd, resin);       // frozen: resin
                res = fmaxf(rc, R0_C);
                thk = __fadd_rn(thk, jd);
                sth[s & 3] = thk; sre[s & 3] = res; scu[s & 3] = jv;
                // ------- convert raws (for t+2) ; MUFU had a full iter -------
                const float su2 = __fmul_rn(up_raw, -SIGMA_C);
                const float lu2 = fmaf(up_raw, -L_C, 2.0f);
                const float nu2 = __fmul_rn(num_of(tfb + (float)(s + 2)), up_raw);
                const bool a2 = (t + 2 >= tstar);
                const float cd2 = a2 ? cvdt : 0.0f;
                const float mj2 = a2 ? mjc0c : 0.0f;
                // ------- issue raws for t+2 (rcp) / t+2 (LDS via te pipe) -------
                const float den = fmaf(SIGMA_C, resin, L_C);          // den_t
                const float dd  = fmaf(2.0f, __fadd_rn(den, -den_prev), den);
                den_prev = den;
                float up_new;
                asm("rcp.approx.f32 %0, %1;" : "=f"(up_new) : "f"(dd));
                const float jp = fmaf(2.0f, __fadd_rn(jv, -j_prev), jv);
                j_prev = jv;
                const float m = fmaf(jp, INVH_F, MAGIC);
                const unsigned iu = min(__float_as_uint(m) & 0x3FFFFFu,
                                        (unsigned)(TABN - 1));
                const float2 te_new = s_tab[iu];                      // LDS
                // ---------------- rotate pipeline (renamed) ----------------
                su0 = su1; lu0 = lu1; nu0 = nu1;
                cvde0 = cvde1; mjc0 = mjc1;
                c0_0 = te1.x; c1_0 = te1.y;
                su1 = su2; lu1 = lu2; nu1 = nu2;
                cvde1 = cd2; mjc1 = mj2;
                te1 = te_raw;
                up_raw = up_new; te_raw = te_new;
                // ---------------- stores every 4 steps ----------------
                if ((s & 3) == 3) {
                    const int b4 = base + (s & ~3);
                    *reinterpret_cast<float4*>(oth + b4) =
                        make_float4(sth[0], sth[1], sth[2], sth[3]);
                    *reinterpret_cast<float4*>(ore + b4) =
                        make_float4(sre[0], sre[1], sre[2], sre[3]);
                    *reinterpret_cast<float4*>(ocu + b4) =
                        make_float4(scu[0], scu[1], scu[2], scu[3]);
                }
            }
        }
    }
}

// ---------------------------------------------------------------------------
// Inputs: Cv, K, jmin, W1, b1, W2, b2, W3, b3
// Output: concat(thickness, resistance, current, time), each (B, NT).
// ---------------------------------------------------------------------------
extern "C" void kernel_launch(void* const* d_in, const int* in_sizes, int n_in,
                              void* d_out, int out_size) {
    const float* Cv = (const float*)d_in[0];
    const float* K  = (const float*)d_in[1];
    const float* jm = (const float*)d_in[2];
    const float* W1 = (const float*)d_in[3];
    const float* b1 = (const float*)d_in[4];
    const float* W2 = (const float*)d_in[5];
    const float* b2 = (const float*)d_in[6];
    const float* W3 = (const float*)d_in[7];
    const float* b3 = (const float*)d_in[8];
    float* out = (float*)d_out;

    time_kernel<<<2048, 256>>>(out + (size_t)3 * B_C * NT_C);
    build_nodes_kernel<<<NODE_BLOCKS + 1, 128>>>(W1, b1, W2, b2, W3, b3);
    build_tab_kernel<<<(TABN + 255) / 256, 256>>>();

    const int smem_bytes = TABN * sizeof(float2) + NT_C * sizeof(float);
    cudaFuncSetAttribute(simulate_kernel,
                         cudaFuncAttributeMaxDynamicSharedMemorySize, smem_bytes);
    simulate_kernel<<<B_C / 32, 32, smem_bytes>>>(Cv, K, jm, out);
}

// round 6
// speedup vs baseline: 2.3346x; 1.0708x over previous
#include <cuda_runtime.h>
#include <cstdint>
#include <math.h>

// ---------------- problem constants ----------------
#define SIGMA_C 0.14f
#define L_C     1.0f
#define R0_C    50.0f
#define DT_C    0.1f
#define NT_C    2000
#define B_C     4096

// rho(j) table: j in [0, 3.5]; res >= 50 invariant => j <= 3.49825
#define TABN   4096
#define NNODES (TABN + 2)
#define JMAX_C 3.5f
#define INVH_F ((float)TABN / JMAX_C)

__device__ float  g_nodes[NNODES];
__device__ float2 g_tab[TABN];    // (c0_k, c1_k): rho(j) = fma(j, c1, c0) near node k
__device__ float  g_Q[NT_C];      // frozen-phase Q prefix (monotone; 1e30 filler)

// exact reference num(t) = 0.14f * (0.1f * t) -- used ONLY for the Q gate
__device__ __forceinline__ float num_exact(float tf) {
    return __fmul_rn(SIGMA_C, __fmul_rn(DT_C, tf));
}

// ---------------------------------------------------------------------------
// build_nodes: exact fp32 MLP rho(x) at table nodes. 4 threads/node, 16 units
// each, W2 in SMEM. Last block (AUX) builds g_Q.
// ---------------------------------------------------------------------------
#define NODE_BLOCKS ((NNODES + 31) / 32)      // 129
#define AUX_BLOCK   NODE_BLOCKS

__global__ void __launch_bounds__(128)
build_nodes_kernel(const float* __restrict__ W1, const float* __restrict__ b1,
                   const float* __restrict__ W2, const float* __restrict__ b2,
                   const float* __restrict__ W3, const float* __restrict__ b3) {
    const int tid = threadIdx.x;

    if (blockIdx.x == AUX_BLOCK) {
        __shared__ float sj[NT_C];
        __shared__ int s_tmax;
        for (int t = tid; t < NT_C; t += 128)
            sj[t] = __fmul_rn(__fmul_rn(num_exact((float)t), 0.125f), DT_C);
        __syncthreads();
        if (tid == 0) {
            float Q = 0.0f;
            g_Q[0] = 0.0f;
            int t = 1;
            for (; t < NT_C; ++t) {
                Q = __fadd_rn(Q, sj[t]);        // exact serial rounding
                g_Q[t] = Q;
                if (Q > 20.0f) { ++t; break; }  // 20 >> max Qmin (~5.7)
            }
            s_tmax = t;
        }
        __syncthreads();
        for (int t = s_tmax + tid; t < NT_C; t += 128) g_Q[t] = 1e30f;
        return;
    }

    __shared__ float sW2[64 * 64];
    __shared__ float sh1[32][64];
    {
        const float4* src = reinterpret_cast<const float4*>(W2);
        float4* dst = reinterpret_cast<float4*>(sW2);
#pragma unroll
        for (int q = 0; q < 8; ++q) dst[tid + 128 * q] = __ldg(src + tid + 128 * q);
    }

    const int nl = tid >> 2;
    const int c  = tid & 3;
    const int node = blockIdx.x * 32 + nl;
    const float H = JMAX_C / (float)TABN;
    const float x = (float)(node - 1) * H;

#pragma unroll
    for (int k = 0; k < 16; ++k) {
        const int u = c * 16 + k;
        sh1[nl][u] = fmaxf(fmaf(x, __ldg(W1 + u), __ldg(b1 + u)), 0.0f);
    }
    __syncthreads();

    float acc[16];
#pragma unroll
    for (int k = 0; k < 16; ++k) acc[k] = __ldg(b2 + c * 16 + k);
#pragma unroll 4
    for (int j = 0; j < 64; ++j) {
        const float hj = sh1[nl][j];
        const float4* row = reinterpret_cast<const float4*>(sW2 + j * 64 + c * 16);
#pragma unroll
        for (int q = 0; q < 4; ++q) {
            const float4 w = row[q];
            acc[q * 4 + 0] = fmaf(hj, w.x, acc[q * 4 + 0]);
            acc[q * 4 + 1] = fmaf(hj, w.y, acc[q * 4 + 1]);
            acc[q * 4 + 2] = fmaf(hj, w.z, acc[q * 4 + 2]);
            acc[q * 4 + 3] = fmaf(hj, w.w, acc[q * 4 + 3]);
        }
    }
    float part = 0.0f;
#pragma unroll
    for (int k = 0; k < 16; ++k)
        part = fmaf(fmaxf(acc[k], 0.0f), __ldg(W3 + c * 16 + k), part);
    part += __shfl_down_sync(0xFFFFFFFFu, part, 2);
    part += __shfl_down_sync(0xFFFFFFFFu, part, 1);
    if (c == 0 && node < NNODES) g_nodes[node] = part + __ldg(b3);
}

__global__ void __launch_bounds__(256)
build_tab_kernel() {
    const int k = blockIdx.x * 256 + threadIdx.x;
    if (k < TABN) {
        const float nm = g_nodes[k], nc = g_nodes[k + 1], np = g_nodes[k + 2];
        const float slope = 0.5f * (np - nm);
        const float c1 = slope * INVH_F;
        const float c0 = fmaf(-slope, (float)k, nc);
        g_tab[k] = make_float2(c0, c1);
    }
}

// ---------------------------------------------------------------------------
// simulate: 1 thread/element, 1 warp/SM. fma-pipe-occupancy-minimized step:
//   chain (reg-fma, rt2): nt1, jv, rho, jd, rc  + Newton carry (tN, u2, nu2)
//   imm-forms (rt1): den, extrapolations, counters, magic index, su/lu
//   alu (idle pipe): fmnmx, AND/LEA for the table index
// No MUFU: 1/den carried by one off-chain Newton per step on extrapolated den
// (in-chain fold squares the error -> j accurate to fp32).
// Phases: frozen (closed form) / transition (per-step gate) / steady (no gate).
// Outputs incl. time staged 4 steps, STG.128.
// ---------------------------------------------------------------------------
extern __shared__ char smem_raw[];
// layout: float2 tab[TABN+2] | float Q[NT_C]

__device__ __forceinline__ uint32_t smem_u32(const void* p) {
    uint32_t a;
    asm("{ .reg .u64 t; cvta.to.shared.u64 t, %1; cvt.u32.u64 %0, t; }"
        : "=r"(a) : "l"(p));
    return a;
}

__global__ void __launch_bounds__(32, 1)
simulate_kernel(const float* __restrict__ Cv, const float* __restrict__ Kp,
                const float* __restrict__ jminp, float* __restrict__ out) {
    const int tid = threadIdx.x;
    const float MAGIC = 12582912.0f;    // 1.5 * 2^23

    float2* s_tab = reinterpret_cast<float2*>(smem_raw);
    float*  sQ    = reinterpret_cast<float*>(smem_raw + (TABN + 2) * sizeof(float2));
    {
        const float4* st4 = reinterpret_cast<const float4*>(g_tab);
        float4* dt4 = reinterpret_cast<float4*>(s_tab);
        for (int i = tid; i < TABN / 2; i += 32) dt4[i] = st4[i];
        const float4* sq4 = reinterpret_cast<const float4*>(g_Q);
        float4* dq4 = reinterpret_cast<float4*>(sQ);
        for (int i = tid; i < NT_C / 4; i += 32) dq4[i] = sq4[i];
        if (tid == 0) {                       // pad (speculative prep reads only)
            s_tab[TABN]     = g_tab[TABN - 1];
            s_tab[TABN + 1] = g_tab[TABN - 1];
        }
    }
    __syncthreads();
    const uint32_t tab32 = smem_u32(s_tab);

    const int e = blockIdx.x * 32 + tid;
    const float cv  = __ldg(Cv + e);
    const float kk  = __ldg(Kp + e);
    const float jmn = __ldg(jminp + e);

    const double beta_d = 0.14 * 1.0 / (0.14 * 50.0 + 1.0);
    const float CQ = (float)pow(81.0 / (128.0 * beta_d), 1.0 / 3.0);
    const float Qmin = CQ * powf(kk, 4.0f / 3.0f);

    // t* = first t with Q_t > Qmin (binary search; Q monotone; tstar >= ~120)
    int lo = 0, hi = NT_C;
    while (hi - lo > 1) {
        const int mid = (lo + hi) >> 1;
        if (sQ[mid] <= Qmin) lo = mid; else hi = mid;
    }
    const int tstar = hi;
    const int tmin  = __reduce_min_sync(0xFFFFFFFFu, tstar);
    const int tmax  = __reduce_max_sync(0xFFFFFFFFu, tstar);

    float res = R0_C, thk = 0.0f;
    const float cvdt = __fmul_rn(cv, DT_C);
    const float mjcC = __fmul_rn(-jmn, cvdt);

    float* oth = out + (size_t)e * NT_C;
    float* ore = oth + (size_t)B_C * NT_C;
    float* ocu = ore + (size_t)B_C * NT_C;
    float* oti = ocu + (size_t)B_C * NT_C;

    const int NTILES = NT_C / 16;
    int fzTiles = tmin / 16;                              // tiles fully frozen
    if (fzTiles > NTILES) fzTiles = NTILES;
    int steadyTile = (tmax + 2 + 15) >> 4;                // first gate-free tile
    if (steadyTile > NTILES) steadyTile = NTILES;
    if (steadyTile < fzTiles) steadyTile = fzTiles;

    float sth[4], sre[4], scu[4];

    // ---------------- phase 1: frozen tiles (closed form) ----------------
    int tile = 0;
    for (; tile < fzTiles; ++tile) {
        const int base = tile * 16;
        const float tfb = (float)base;
#pragma unroll
        for (int q = 0; q < 4; ++q) {
            const float t0 = tfb + (float)(4 * q);
            float j0 = __fmul_rn(t0, 0.00175f);                    // num/8
            if (tile == 0 && q == 0) j0 = 1e-3f;                   // t = 0
            const int b4 = base + 4 * q;
            *reinterpret_cast<float4*>(oth + b4) = make_float4(0.f, 0.f, 0.f, 0.f);
            *reinterpret_cast<float4*>(ore + b4) =
                make_float4(R0_C, R0_C, R0_C, R0_C);
            *reinterpret_cast<float4*>(ocu + b4) =
                make_float4(j0,
                            __fmul_rn(t0 + 1.0f, 0.00175f),
                            __fmul_rn(t0 + 2.0f, 0.00175f),
                            __fmul_rn(t0 + 3.0f, 0.00175f));
            *reinterpret_cast<float4*>(oti + b4) =
                make_float4(__fmul_rn(DT_C, t0),
                            __fmul_rn(DT_C, t0 + 1.0f),
                            __fmul_rn(DT_C, t0 + 2.0f),
                            __fmul_rn(DT_C, t0 + 3.0f));
        }
    }

    // ---------------- pipeline init at t0 = fzTiles*16 ----------------
    const int t0i = tile * 16;
    const float tf0 = (float)t0i;
    float uc0 = 0.125f, uc1 = 0.125f;                     // exact 1/8
    float su0 = -0.0175f, su1 = -0.0175f;                 // -sigma/8 exact
    float lu0 = 1.875f,  lu1 = 1.875f;                    // 2 - 1/8 exact
    float nu0 = __fmul_rn(__fmul_rn(tf0,        0.014f), 0.125f);
    float nu1 = __fmul_rn(__fmul_rn(tf0 + 1.0f, 0.014f), 0.125f);
    float den_prev = 8.0f;
    float j_prev = __fmul_rn(tf0 - 1.0f, 0.00175f);
    float tcp = tf0 + 2.0f;                               // t being prepped
    float c00, c10;  float2 te1, te_raw;
#pragma unroll
    for (int k = 0; k < 3; ++k) {
        const float jk = __fmul_rn(tf0 + (float)k, 0.00175f);
        const float m  = fmaf(jk, INVH_F, MAGIC);
        const uint32_t off = (__float_as_uint(m) & 0x3FFFFFu) * 8u;
        float a, b;
        asm volatile("ld.shared.v2.f32 {%0, %1}, [%2];"
                     : "=f"(a), "=f"(b) : "r"(tab32 + off));
        if (k == 0) { c00 = a; c10 = b; }
        else if (k == 1) { te1.x = a; te1.y = b; }
        else { te_raw.x = a; te_raw.y = b; }
    }
    float cvde0 = (t0i     >= tstar) ? cvdt : 0.0f;
    float mjc0  = (t0i     >= tstar) ? mjcC : 0.0f;
    float cvde1 = (t0i + 1 >= tstar) ? cvdt : 0.0f;
    float mjc1  = (t0i + 1 >= tstar) ? mjcC : 0.0f;

    // ---------------- phase 2: transition tiles (per-step gate) ----------------
    for (; tile < steadyTile; ++tile) {
        const int base = tile * 16;
        const float tfb = (float)base;
#pragma unroll
        for (int s = 0; s < 16; ++s) {
            const int t = base + s;
            const float resin = res;
            const float nt1 = fmaf(resin, su0, lu0);
            const float jv  = __fmul_rn(nu0, nt1);
            const float rho = fmaf(jv, c10, c00);
            const float jd  = fmaf(jv, cvde0, mjc0);
            const float rc  = fmaf(rho, jd, resin);
            res = fmaxf(rc, R0_C);
            thk = fmaxf(thk + jd, 0.0f);
            sth[s & 3] = thk; sre[s & 3] = res; scu[s & 3] = jv;
            // prep t+2
            const float den = fmaf(resin, SIGMA_C, 1.0f);
            const float dif = den - den_prev;
            const float dd  = fmaf(2.0f, dif, den);
            den_prev = den;
            const float tN = fmaf(-dd, uc0, 2.0f);
            const float u2 = __fmul_rn(uc0, tN);
            const float su2 = __fmul_rn(u2, -SIGMA_C);
            const float lu2 = 2.0f - u2;
            const float nu2 = __fmul_rn(__fmul_rn(tcp, 0.014f), u2);
            const float jdf = jv - j_prev;
            const float jp  = fmaxf(fmaf(2.0f, jdf, jv), 0.0f);
            j_prev = jv;
            const float m = fmaf(jp, INVH_F, MAGIC);
            const uint32_t off = (__float_as_uint(m) & 0x3FFFFFu) * 8u;
            float na, nb;
            asm volatile("ld.shared.v2.f32 {%0, %1}, [%2];"
                         : "=f"(na), "=f"(nb) : "r"(tab32 + off));
            const bool a2 = (t + 2 >= tstar);
            const float cd2 = a2 ? cvdt : 0.0f;
            const float mj2 = a2 ? mjcC : 0.0f;
            // rotate
            su0 = su1; lu0 = lu1; nu0 = nu1; uc0 = uc1;
            c00 = te1.x; c10 = te1.y;
            cvde0 = cvde1; mjc0 = mjc1;
            su1 = su2; lu1 = lu2; nu1 = nu2; uc1 = u2;
            te1 = te_raw; te_raw.x = na; te_raw.y = nb;
            cvde1 = cd2; mjc1 = mj2;
            tcp += 1.0f;
            if ((s & 3) == 3) {
                const int b4 = base + (s & ~3);
                const float tq = tfb + (float)(s & ~3);
                *reinterpret_cast<float4*>(oth + b4) =
                    make_float4(sth[0], sth[1], sth[2], sth[3]);
                *reinterpret_cast<float4*>(ore + b4) =
                    make_float4(sre[0], sre[1], sre[2], sre[3]);
                *reinterpret_cast<float4*>(ocu + b4) =
                    make_float4(scu[0], scu[1], scu[2], scu[3]);
                *reinterpret_cast<float4*>(oti + b4) =
                    make_float4(__fmul_rn(DT_C, tq),
                                __fmul_rn(DT_C, tq + 1.0f),
                                __fmul_rn(DT_C, tq + 2.0f),
                                __fmul_rn(DT_C, tq + 3.0f));
            }
        }
    }

    // ---------------- phase 3: steady tiles (gate constant) ----------------
    for (; tile < NTILES; ++tile) {
        const int base = tile * 16;
        const float tfb = (float)base;
#pragma unroll
        for (int s = 0; s < 16; ++s) {
            const float resin = res;
            const float nt1 = fmaf(resin, su0, lu0);
            const float jv  = __fmul_rn(nu0, nt1);
            const float rho = fmaf(jv, c10, c00);
            const float jd  = fmaf(jv, cvdt, mjcC);
            const float rc  = fmaf(rho, jd, resin);
            res = fmaxf(rc, R0_C);
            thk = fmaxf(thk + jd, 0.0f);
            sth[s & 3] = thk; sre[s & 3] = res; scu[s & 3] = jv;
            // prep t+2
            const float den = fmaf(resin, SIGMA_C, 1.0f);
            const float dif = den - den_prev;
            const float dd  = fmaf(2.0f, dif, den);
            den_prev = den;
            const float tN = fmaf(-dd, uc0, 2.0f);
            const float u2 = __fmul_rn(uc0, tN);
            const float su2 = __fmul_rn(u2, -SIGMA_C);
            const float lu2 = 2.0f - u2;
            const float nu2 = __fmul_rn(__fmul_rn(tcp, 0.014f), u2);
            const float jdf = jv - j_prev;
            const float jp  = fmaxf(fmaf(2.0f, jdf, jv), 0.0f);
            j_prev = jv;
            const float m = fmaf(jp, INVH_F, MAGIC);
            const uint32_t off = (__float_as_uint(m) & 0x3FFFFFu) * 8u;
            float na, nb;
            asm volatile("ld.shared.v2.f32 {%0, %1}, [%2];"
                         : "=f"(na), "=f"(nb) : "r"(tab32 + off));
            // rotate
            su0 = su1; lu0 = lu1; nu0 = nu1; uc0 = uc1;
            c00 = te1.x; c10 = te1.y;
            su1 = su2; lu1 = lu2; nu1 = nu2; uc1 = u2;
            te1 = te_raw; te_raw.x = na; te_raw.y = nb;
            tcp += 1.0f;
            if ((s & 3) == 3) {
                const int b4 = base + (s & ~3);
                const float tq = tfb + (float)(s & ~3);
                *reinterpret_cast<float4*>(oth + b4) =
                    make_float4(sth[0], sth[1], sth[2], sth[3]);
                *reinterpret_cast<float4*>(ore + b4) =
                    make_float4(sre[0], sre[1], sre[2], sre[3]);
                *reinterpret_cast<float4*>(ocu + b4) =
                    make_float4(scu[0], scu[1], scu[2], scu[3]);
                *reinterpret_cast<float4*>(oti + b4) =
                    make_float4(__fmul_rn(DT_C, tq),
                                __fmul_rn(DT_C, tq + 1.0f),
                                __fmul_rn(DT_C, tq + 2.0f),
                                __fmul_rn(DT_C, tq + 3.0f));
            }
        }
    }
}

// ---------------------------------------------------------------------------
// Inputs: Cv, K, jmin, W1, b1, W2, b2, W3, b3
// Output: concat(thickness, resistance, current, time), each (B, NT).
// ---------------------------------------------------------------------------
extern "C" void kernel_launch(void* const* d_in, const int* in_sizes, int n_in,
                              void* d_out, int out_size) {
    const float* Cv = (const float*)d_in[0];
    const float* K  = (const float*)d_in[1];
    const float* jm = (const float*)d_in[2];
    const float* W1 = (const float*)d_in[3];
    const float* b1 = (const float*)d_in[4];
    const float* W2 = (const float*)d_in[5];
    const float* b2 = (const float*)d_in[6];
    const float* W3 = (const float*)d_in[7];
    const float* b3 = (const float*)d_in[8];
    float* out = (float*)d_out;

    build_nodes_kernel<<<NODE_BLOCKS + 1, 128>>>(W1, b1, W2, b2, W3, b3);
    build_tab_kernel<<<(TABN + 255) / 256, 256>>>();

    const int smem_bytes = (TABN + 2) * sizeof(float2) + NT_C * sizeof(float);
    cudaFuncSetAttribute(simulate_kernel,
                         cudaFuncAttributeMaxDynamicSharedMemorySize, smem_bytes);
    simulate_kernel<<<B_C / 32, 32, smem_bytes>>>(Cv, K, jm, out);
}

// round 7
// speedup vs baseline: 2.8464x; 1.2192x over previous
#include <cuda_runtime.h>
#include <cstdint>
#include <math.h>

// ---------------- problem constants ----------------
#define SIGMA_C 0.14f
#define L_C     1.0f
#define R0_C    50.0f
#define DT_C    0.1f
#define NT_C    2000
#define B_C     4096

// rho(j) table: j in [0, 3.5]; res >= 50 invariant => j <= 3.49825
#define TABN   4096
#define NNODES (TABN + 2)
#define JMAX_C 3.5f
#define INVH_F ((float)TABN / JMAX_C)

__device__ float  g_nodes[NNODES];
__device__ float2 g_tab[TABN];    // (c0_k, c1_k): rho(j) = fma(j, c1, c0) near node k
__device__ float  g_Q[NT_C];      // frozen-phase Q prefix (monotone; 1e30 filler)

// ---------------------------------------------------------------------------
// build_nodes: exact fp32 MLP rho(x) at table nodes. 4 threads/node, 16 units
// each, W2 in SMEM. Last block (AUX) builds g_Q with a register-only serial
// chain (increments computed inline in exact reference rounding order; the
// loop breaks at Q>20 ~ t=478, so ~500 FADDs total).
// ---------------------------------------------------------------------------
#define NODE_BLOCKS ((NNODES + 31) / 32)      // 129
#define AUX_BLOCK   NODE_BLOCKS

__device__ __forceinline__ float q_inc(float tf) {
    // ((0.14f * (0.1f * t)) * 0.125f) * 0.1f  -- exact reference order
    return __fmul_rn(__fmul_rn(__fmul_rn(SIGMA_C, __fmul_rn(DT_C, tf)),
                               0.125f), DT_C);
}

__global__ void __launch_bounds__(128)
build_nodes_kernel(const float* __restrict__ W1, const float* __restrict__ b1,
                   const float* __restrict__ W2, const float* __restrict__ b2,
                   const float* __restrict__ W3, const float* __restrict__ b3) {
    const int tid = threadIdx.x;

    if (blockIdx.x == AUX_BLOCK) {
        __shared__ int s_tmax;
        if (tid == 0) {
            float Q = 0.0f;
            g_Q[0] = 0.0f;
            int t = 1;
            while (t + 3 < NT_C) {
                const float f0 = (float)t;
                const float i0 = q_inc(f0);
                const float i1 = q_inc(f0 + 1.0f);
                const float i2 = q_inc(f0 + 2.0f);
                const float i3 = q_inc(f0 + 3.0f);
                Q = __fadd_rn(Q, i0); g_Q[t]     = Q;
                Q = __fadd_rn(Q, i1); g_Q[t + 1] = Q;
                Q = __fadd_rn(Q, i2); g_Q[t + 2] = Q;
                Q = __fadd_rn(Q, i3); g_Q[t + 3] = Q;
                t += 4;
                if (Q > 20.0f) break;           // 20 >> max Qmin (~5.7)
            }
            while (t < NT_C && g_Q[t - 1] <= 20.0f) {
                Q = __fadd_rn(Q, q_inc((float)t));
                g_Q[t] = Q; ++t;
            }
            s_tmax = t;
        }
        __syncthreads();
        for (int t = s_tmax + tid; t < NT_C; t += 128) g_Q[t] = 1e30f;
        return;
    }

    __shared__ float sW2[64 * 64];
    __shared__ float sh1[32][64];
    {
        const float4* src = reinterpret_cast<const float4*>(W2);
        float4* dst = reinterpret_cast<float4*>(sW2);
#pragma unroll
        for (int q = 0; q < 8; ++q) dst[tid + 128 * q] = __ldg(src + tid + 128 * q);
    }

    const int nl = tid >> 2;
    const int c  = tid & 3;
    const int node = blockIdx.x * 32 + nl;
    const float H = JMAX_C / (float)TABN;
    const float x = (float)(node - 1) * H;

#pragma unroll
    for (int k = 0; k < 16; ++k) {
        const int u = c * 16 + k;
        sh1[nl][u] = fmaxf(fmaf(x, __ldg(W1 + u), __ldg(b1 + u)), 0.0f);
    }
    __syncthreads();

    float acc[16];
#pragma unroll
    for (int k = 0; k < 16; ++k) acc[k] = __ldg(b2 + c * 16 + k);
#pragma unroll 4
    for (int j = 0; j < 64; ++j) {
        const float hj = sh1[nl][j];
        const float4* row = reinterpret_cast<const float4*>(sW2 + j * 64 + c * 16);
#pragma unroll
        for (int q = 0; q < 4; ++q) {
            const float4 w = row[q];
            acc[q * 4 + 0] = fmaf(hj, w.x, acc[q * 4 + 0]);
            acc[q * 4 + 1] = fmaf(hj, w.y, acc[q * 4 + 1]);
            acc[q * 4 + 2] = fmaf(hj, w.z, acc[q * 4 + 2]);
            acc[q * 4 + 3] = fmaf(hj, w.w, acc[q * 4 + 3]);
        }
    }
    float part = 0.0f;
#pragma unroll
    for (int k = 0; k < 16; ++k)
        part = fmaf(fmaxf(acc[k], 0.0f), __ldg(W3 + c * 16 + k), part);
    part += __shfl_down_sync(0xFFFFFFFFu, part, 2);
    part += __shfl_down_sync(0xFFFFFFFFu, part, 1);
    if (c == 0 && node < NNODES) g_nodes[node] = part + __ldg(b3);
}

__global__ void __launch_bounds__(256)
build_tab_kernel() {
    const int k = blockIdx.x * 256 + threadIdx.x;
    if (k < TABN) {
        const float nm = g_nodes[k], nc = g_nodes[k + 1], np = g_nodes[k + 2];
        const float slope = 0.5f * (np - nm);
        const float c1 = slope * INVH_F;
        const float c0 = fmaf(-slope, (float)k, nc);
        g_tab[k] = make_float2(c0, c1);
    }
}

// ---------------------------------------------------------------------------
// simulate: 64 threads/CTA. Warp 0 computes (1 lane = 1 element), staging
// (thk,res,j) tiles of 16 steps into a double-buffered SMEM region via
// STS.128. Warp 1 (its own SMSP) drains buffers to GMEM with STG.128 and
// writes the time array directly — the STG issue tax leaves the compute warp.
// Chain: den(imm fma) -> w=fma(den,-u,2) -> j=nu*w -> rho/jd -> rc -> fmnmx.
// u (~1/den) carried by one off-chain Newton on the extrapolated den; the
// in-chain fold is a second Newton -> j fp32-exact. Frozen phase bit-exact.
// ---------------------------------------------------------------------------
#define TAB_BYTES  ((TABN + 2) * 8)           // 32784
#define Q_OFF      TAB_BYTES
#define BUF_OFF    40832                      // align(TAB_BYTES + 8000, 128)
#define BUF_P      6144                       // bytes per buffer (3 arrays)
#define BUF_ARR    2048                       // bytes per array (4 q * 512)
#define SMEM_TOTAL (BUF_OFF + 2 * BUF_P)      // 53120

extern __shared__ char smem_raw[];

__device__ __forceinline__ uint32_t smem_u32(const void* p) {
    uint32_t a;
    asm("{ .reg .u64 t; cvta.to.shared.u64 t, %1; cvt.u32.u64 %0, t; }"
        : "=r"(a) : "l"(p));
    return a;
}
__device__ __forceinline__ void sts128(uint32_t a, float x, float y, float z, float w) {
    asm volatile("st.shared.v4.f32 [%0], {%1, %2, %3, %4};"
                 :: "r"(a), "f"(x), "f"(y), "f"(z), "f"(w) : "memory");
}
__device__ __forceinline__ float4 lds128(uint32_t a) {
    float4 v;
    asm volatile("ld.shared.v4.f32 {%0, %1, %2, %3}, [%4];"
                 : "=f"(v.x), "=f"(v.y), "=f"(v.z), "=f"(v.w) : "r"(a));
    return v;
}
#define BAR_SYNC(id)   asm volatile("bar.sync %0, 64;"   :: "r"(id) : "memory")
#define BAR_ARRIVE(id) asm volatile("bar.arrive %0, 64;" :: "r"(id) : "memory")

__global__ void __launch_bounds__(64, 1)
simulate_kernel(const float* __restrict__ Cv, const float* __restrict__ Kp,
                const float* __restrict__ jminp, float* __restrict__ out) {
    const int tid  = threadIdx.x;
    const int lane = tid & 31;
    const int wid  = tid >> 5;
    const float MAGIC = 12582912.0f;    // 1.5 * 2^23

    float2* s_tab = reinterpret_cast<float2*>(smem_raw);
    float*  sQ    = reinterpret_cast<float*>(smem_raw + Q_OFF);
    {
        const float4* st4 = reinterpret_cast<const float4*>(g_tab);
        float4* dt4 = reinterpret_cast<float4*>(s_tab);
        for (int i = tid; i < TABN / 2; i += 64) dt4[i] = st4[i];
        const float4* sq4 = reinterpret_cast<const float4*>(g_Q);
        float4* dq4 = reinterpret_cast<float4*>(sQ);
        for (int i = tid; i < NT_C / 4; i += 64) dq4[i] = sq4[i];
        if (tid == 0) { s_tab[TABN] = g_tab[TABN - 1]; s_tab[TABN + 1] = g_tab[TABN - 1]; }
    }
    __syncthreads();
    const uint32_t tab32 = smem_u32(s_tab);
    const uint32_t buf32 = smem_u32(smem_raw + BUF_OFF);

    const int e = blockIdx.x * 32 + lane;
    const float cv  = __ldg(Cv + e);
    const float kk  = __ldg(Kp + e);
    const float jmn = __ldg(jminp + e);

    const double beta_d = 0.14 * 1.0 / (0.14 * 50.0 + 1.0);
    const float CQ = (float)pow(81.0 / (128.0 * beta_d), 1.0 / 3.0);
    const float Qmin = CQ * powf(kk, 4.0f / 3.0f);

    // t* = first t with Q_t > Qmin (binary search; Q monotone)
    int lo = 0, hi = NT_C;
    while (hi - lo > 1) {
        const int mid = (lo + hi) >> 1;
        if (sQ[mid] <= Qmin) lo = mid; else hi = mid;
    }
    const int tstar = hi;
    const int tmin  = __reduce_min_sync(0xFFFFFFFFu, tstar);
    const int tmax  = __reduce_max_sync(0xFFFFFFFFu, tstar);

    const int NTILES = NT_C / 16;
    int fzTiles = tmin / 16;
    if (fzTiles > NTILES) fzTiles = NTILES;
    int steadyTile = (tmax + 2 + 15) >> 4;
    if (steadyTile > NTILES) steadyTile = NTILES;
    if (steadyTile < fzTiles) steadyTile = fzTiles;

    if (wid == 1) {
        // =================== writer warp ===================
        float* oth = out + (size_t)e * NT_C;
        float* ore = oth + (size_t)B_C * NT_C;
        float* ocu = ore + (size_t)B_C * NT_C;
        float* oti = ocu + (size_t)B_C * NT_C;

        // frozen tiles: closed form, written directly
        for (int tile = 0; tile < fzTiles; ++tile) {
            const int base = tile * 16;
            const float tfb = (float)base;
#pragma unroll
            for (int q = 0; q < 4; ++q) {
                const float t0 = tfb + (float)(4 * q);
                float j0 = __fmul_rn(t0, 0.00175f);
                if (tile == 0 && q == 0) j0 = 1e-3f;
                const int b4 = base + 4 * q;
                *reinterpret_cast<float4*>(oth + b4) = make_float4(0.f, 0.f, 0.f, 0.f);
                *reinterpret_cast<float4*>(ore + b4) =
                    make_float4(R0_C, R0_C, R0_C, R0_C);
                *reinterpret_cast<float4*>(ocu + b4) =
                    make_float4(j0,
                                __fmul_rn(t0 + 1.0f, 0.00175f),
                                __fmul_rn(t0 + 2.0f, 0.00175f),
                                __fmul_rn(t0 + 3.0f, 0.00175f));
                *reinterpret_cast<float4*>(oti + b4) =
                    make_float4(__fmul_rn(DT_C, t0),
                                __fmul_rn(DT_C, t0 + 1.0f),
                                __fmul_rn(DT_C, t0 + 2.0f),
                                __fmul_rn(DT_C, t0 + 3.0f));
            }
        }
        // prime the free barriers (one per buffer)
        BAR_ARRIVE(3);
        BAR_ARRIVE(4);
        const uint32_t lb = buf32 + lane * 16;
        for (int tile = fzTiles; tile < NTILES; ++tile) {
            const int p = tile & 1;
            BAR_SYNC(1 + p);                         // wait buffer ready
            const uint32_t bp = lb + p * BUF_P;
            const int base = tile * 16;
            const float tfb = (float)base;
#pragma unroll
            for (int q = 0; q < 4; ++q) {
                const float4 a = lds128(bp + 0 * BUF_ARR + q * 512);
                const float4 b = lds128(bp + 1 * BUF_ARR + q * 512);
                const float4 c = lds128(bp + 2 * BUF_ARR + q * 512);
                *reinterpret_cast<float4*>(oth + base + 4 * q) = a;
                *reinterpret_cast<float4*>(ore + base + 4 * q) = b;
                *reinterpret_cast<float4*>(ocu + base + 4 * q) = c;
                const float tq = tfb + (float)(4 * q);
                *reinterpret_cast<float4*>(oti + base + 4 * q) =
                    make_float4(__fmul_rn(DT_C, tq),
                                __fmul_rn(DT_C, tq + 1.0f),
                                __fmul_rn(DT_C, tq + 2.0f),
                                __fmul_rn(DT_C, tq + 3.0f));
            }
            BAR_ARRIVE(3 + p);                       // buffer free
        }
        return;
    }

    // =================== compute warp ===================
    float res = R0_C, thk = 0.0f;
    const float cvdt = __fmul_rn(cv, DT_C);
    const float mjcC = __fmul_rn(-jmn, cvdt);

    const int t0i = fzTiles * 16;
    const float tf0 = (float)t0i;
    float uc0 = 0.125f, uc1 = 0.125f;                 // exact 1/8
    float nu0 = __fmul_rn(__fmul_rn(tf0,        0.014f), 0.125f);
    float nu1 = __fmul_rn(__fmul_rn(tf0 + 1.0f, 0.014f), 0.125f);
    float den_prev = 8.0f;
    float j_prev = __fmul_rn(tf0 - 1.0f, 0.00175f);
    float tcp = tf0 + 2.0f;
    float c00, c10;  float2 te1, te_raw;
#pragma unroll
    for (int k = 0; k < 3; ++k) {
        const float jk = __fmul_rn(tf0 + (float)k, 0.00175f);
        const float m  = fmaf(jk, INVH_F, MAGIC);
        uint32_t iu = __float_as_uint(m) & 0x3FFFFFu;
        iu = min(iu, (uint32_t)(TABN - 1));
        const float2 te = s_tab[iu];
        if (k == 0) { c00 = te.x; c10 = te.y; }
        else if (k == 1) te1 = te;
        else te_raw = te;
    }
    float cvde0 = (t0i     >= tstar) ? cvdt : 0.0f;
    float mjc0  = (t0i     >= tstar) ? mjcC : 0.0f;
    float cvde1 = (t0i + 1 >= tstar) ? cvdt : 0.0f;
    float mjc1  = (t0i + 1 >= tstar) ? mjcC : 0.0f;

    const uint32_t sb = buf32 + lane * 16;
    float sth[4], sre[4], scu[4];

    int tile = fzTiles;
    // -------- transition tiles (per-step gate) --------
    for (; tile < steadyTile; ++tile) {
        const int p = tile & 1;
        BAR_SYNC(3 + p);                              // wait buffer free
        const uint32_t bp = sb + p * BUF_P;
        const int base = tile * 16;
#pragma unroll
        for (int s = 0; s < 16; ++s) {
            const int t = base + s;
            const float resin = res;
            const float den = fmaf(resin, SIGMA_C, 1.0f);
            const float w   = fmaf(den, -uc0, 2.0f);   // in-chain Newton fold
            const float jv  = __fmul_rn(nu0, w);
            const float rho = fmaf(jv, c10, c00);
            const float jd  = fmaf(jv, cvde0, mjc0);   // frozen: exactly 0
            const float rc  = fmaf(rho, jd, resin);
            res = fmaxf(rc, R0_C);
            thk = fmaxf(thk + jd, 0.0f);
            sth[s & 3] = thk; sre[s & 3] = res; scu[s & 3] = jv;
            // prep step t+2
            const float dif = den - den_prev;
            const float dd  = fmaf(dif, 2.0f, den);
            den_prev = den;
            const float tN  = fmaf(dd, -uc1, 2.0f);    // off-chain Newton
            const float u2  = __fmul_rn(uc1, tN);
            const float nu2 = __fmul_rn(__fmul_rn(tcp, 0.014f), u2);
            const float jdf = jv - j_prev;
            const float jp  = fmaxf(fmaf(jdf, 2.0f, jv), 0.0f);
            j_prev = jv;
            const float m = fmaf(jp, INVH_F, MAGIC);
            uint32_t iu = __float_as_uint(m) & 0x3FFFFFu;
            iu = min(iu, (uint32_t)(TABN - 1));
            float na, nb;
            asm volatile("ld.shared.v2.f32 {%0, %1}, [%2];"
                         : "=f"(na), "=f"(nb) : "r"(tab32 + iu * 8u));
            const bool a2 = (t + 2 >= tstar);
            const float cd2 = a2 ? cvdt : 0.0f;
            const float mj2 = a2 ? mjcC : 0.0f;
            // rotate (renamed by unroll)
            uc0 = uc1; uc1 = u2;
            nu0 = nu1; nu1 = nu2;
            c00 = te1.x; c10 = te1.y;
            te1 = te_raw; te_raw.x = na; te_raw.y = nb;
            cvde0 = cvde1; mjc0 = mjc1;
            cvde1 = cd2;  mjc1 = mj2;
            tcp += 1.0f;
            if ((s & 3) == 3) {
                const uint32_t qo = (uint32_t)(s >> 2) * 512u;
                sts128(bp + 0 * BUF_ARR + qo, sth[0], sth[1], sth[2], sth[3]);
                sts128(bp + 1 * BUF_ARR + qo, sre[0], sre[1], sre[2], sre[3]);
                sts128(bp + 2 * BUF_ARR + qo, scu[0], scu[1], scu[2], scu[3]);
            }
        }
        BAR_ARRIVE(1 + p);                            // buffer ready
    }
    // -------- steady tiles (all lanes crossed; gate constant) --------
    for (; tile < NTILES; ++tile) {
        const int p = tile & 1;
        BAR_SYNC(3 + p);
        const uint32_t bp = sb + p * BUF_P;
#pragma unroll
        for (int s = 0; s < 16; ++s) {
            const float resin = res;
            const float den = fmaf(resin, SIGMA_C, 1.0f);
            const float w   = fmaf(den, -uc0, 2.0f);
            const float jv  = __fmul_rn(nu0, w);
            const float rho = fmaf(jv, c10, c00);
            const float jd  = fmaf(jv, cvdt, mjcC);
            const float rc  = fmaf(rho, jd, resin);
            res = fmaxf(rc, R0_C);
            thk = fmaxf(thk + jd, 0.0f);
            sth[s & 3] = thk; sre[s & 3] = res; scu[s & 3] = jv;
            // prep step t+2
            const float dif = den - den_prev;
            const float dd  = fmaf(dif, 2.0f, den);
            den_prev = den;
            const float tN  = fmaf(dd, -uc1, 2.0f);
            const float u2  = __fmul_rn(uc1, tN);
            const float nu2 = __fmul_rn(__fmul_rn(tcp, 0.014f), u2);
            const float jdf = jv - j_prev;
            const float jp  = fmaxf(fmaf(jdf, 2.0f, jv), 0.0f);
            j_prev = jv;
            const float m = fmaf(jp, INVH_F, MAGIC);
            uint32_t iu = __float_as_uint(m) & 0x3FFFFFu;
            iu = min(iu, (uint32_t)(TABN - 1));
            float na, nb;
            asm volatile("ld.shared.v2.f32 {%0, %1}, [%2];"
                         : "=f"(na), "=f"(nb) : "r"(tab32 + iu * 8u));
            // rotate
            uc0 = uc1; uc1 = u2;
            nu0 = nu1; nu1 = nu2;
            c00 = te1.x; c10 = te1.y;
            te1 = te_raw; te_raw.x = na; te_raw.y = nb;
            tcp += 1.0f;
            if ((s & 3) == 3) {
                const uint32_t qo = (uint32_t)(s >> 2) * 512u;
                sts128(bp + 0 * BUF_ARR + qo, sth[0], sth[1], sth[2], sth[3]);
                sts128(bp + 1 * BUF_ARR + qo, sre[0], sre[1], sre[2], sre[3]);
                sts128(bp + 2 * BUF_ARR + qo, scu[0], scu[1], scu[2], scu[3]);
            }
        }
        BAR_ARRIVE(1 + p);
    }
}

// ---------------------------------------------------------------------------
// Inputs: Cv, K, jmin, W1, b1, W2, b2, W3, b3
// Output: concat(thickness, resistance, current, time), each (B, NT).
// ---------------------------------------------------------------------------
extern "C" void kernel_launch(void* const* d_in, const int* in_sizes, int n_in,
                              void* d_out, int out_size) {
    const float* Cv = (const float*)d_in[0];
    const float* K  = (const float*)d_in[1];
    const float* jm = (const float*)d_in[2];
    const float* W1 = (const float*)d_in[3];
    const float* b1 = (const float*)d_in[4];
    const float* W2 = (const float*)d_in[5];
    const float* b2 = (const float*)d_in[6];
    const float* W3 = (const float*)d_in[7];
    const float* b3 = (const float*)d_in[8];
    float* out = (float*)d_out;

    build_nodes_kernel<<<NODE_BLOCKS + 1, 128>>>(W1, b1, W2, b2, W3, b3);
    build_tab_kernel<<<(TABN + 255) / 256, 256>>>();

    cudaFuncSetAttribute(simulate_kernel,
                         cudaFuncAttributeMaxDynamicSharedMemorySize, SMEM_TOTAL);
    simulate_kernel<<<B_C / 32, 64, SMEM_TOTAL>>>(Cv, K, jm, out);
}

// round 8
// speedup vs baseline: 3.0096x; 1.0574x over previous
#include <cuda_runtime.h>
#include <cstdint>
#include <math.h>

// ---------------- problem constants ----------------
#define SIGMA_C 0.14f
#define L_C     1.0f
#define R0_C    50.0f
#define DT_C    0.1f
#define NT_C    2000
#define B_C     4096

// rho(j) table: j in [0, 3.5]; res >= 50 invariant => j <= 3.49825
#define TABN   4096
#define NNODES (TABN + 2)
#define JMAX_C 3.5f
#define INVH_F ((float)TABN / JMAX_C)

// frozen prefix: K >= 0.5 -> Qmin >= 1.311 > Q(112) = 1.107  => t* >= 113
#define T_FROZEN 112
#define TILE_S   32
#define NTILES_A ((NT_C - T_FROZEN) / TILE_S)    // 59
// Q prefix needed only to t <= 256 (Qmin < 5.69; Q(256) = 5.757)
#define QLEN 272

__device__ float g_nodes[NNODES];

// ---------------------------------------------------------------------------
// build_nodes: exact fp32 MLP rho(x) at table nodes. 4 threads/node, 16 units
// each, W2 in SMEM, sh1 padded to 65 to kill the 8-way bank conflict.
// ---------------------------------------------------------------------------
#define NODE_BLOCKS ((NNODES + 31) / 32)      // 129

__global__ void __launch_bounds__(128)
build_nodes_kernel(const float* __restrict__ W1, const float* __restrict__ b1,
                   const float* __restrict__ W2, const float* __restrict__ b2,
                   const float* __restrict__ W3, const float* __restrict__ b3) {
    const int tid = threadIdx.x;
    __shared__ float sW2[64 * 64];
    __shared__ float sh1[32][65];             // pad: (nl*65+j)%32 distinct per nl
    {
        const float4* src = reinterpret_cast<const float4*>(W2);
        float4* dst = reinterpret_cast<float4*>(sW2);
#pragma unroll
        for (int q = 0; q < 8; ++q) dst[tid + 128 * q] = __ldg(src + tid + 128 * q);
    }

    const int nl = tid >> 2;
    const int c  = tid & 3;
    const int node = blockIdx.x * 32 + nl;
    const float H = JMAX_C / (float)TABN;
    const float x = (float)(node - 1) * H;

#pragma unroll
    for (int k = 0; k < 16; ++k) {
        const int u = c * 16 + k;
        sh1[nl][u] = fmaxf(fmaf(x, __ldg(W1 + u), __ldg(b1 + u)), 0.0f);
    }
    __syncthreads();

    float acc[16];
#pragma unroll
    for (int k = 0; k < 16; ++k) acc[k] = __ldg(b2 + c * 16 + k);
#pragma unroll 4
    for (int j = 0; j < 64; ++j) {
        const float hj = sh1[nl][j];
        const float4* row = reinterpret_cast<const float4*>(sW2 + j * 64 + c * 16);
#pragma unroll
        for (int q = 0; q < 4; ++q) {
            const float4 w = row[q];
            acc[q * 4 + 0] = fmaf(hj, w.x, acc[q * 4 + 0]);
            acc[q * 4 + 1] = fmaf(hj, w.y, acc[q * 4 + 1]);
            acc[q * 4 + 2] = fmaf(hj, w.z, acc[q * 4 + 2]);
            acc[q * 4 + 3] = fmaf(hj, w.w, acc[q * 4 + 3]);
        }
    }
    float part = 0.0f;
#pragma unroll
    for (int k = 0; k < 16; ++k)
        part = fmaf(fmaxf(acc[k], 0.0f), __ldg(W3 + c * 16 + k), part);
    part += __shfl_down_sync(0xFFFFFFFFu, part, 2);
    part += __shfl_down_sync(0xFFFFFFFFu, part, 1);
    if (c == 0 && node < NNODES) g_nodes[node] = part + __ldg(b3);
}

// ---------------------------------------------------------------------------
// simulate: 64 threads/CTA. Warp 0 computes, warp 1 drains SMEM buffers to
// GMEM (plus the provably-frozen first 112 steps + the time array).
// Per-step chain (20 cyc): den(imm fma) -> j = fma(den,-p,q) -> {rho, jd}
//   -> rc -> fmnmx.   (p = nu*u, q = 2*nu precomputed off-chain; the fold is
//   the Newton correction of the self-Newton-carried u ~ 1/den.)
// Table index taken from nu2 (= predicted j_{t+2}) -> prediction path deleted.
// Init (tab build from g_nodes, exact serial Q prefix, binary-searched t*)
// overlaps with the writer's frozen-region stores.
// ---------------------------------------------------------------------------
#define TAB_BYTES  (TABN * 8)                  // 32768
#define Q_OFF      TAB_BYTES                   // float[QLEN]
#define BUF_OFF    33920                       // 128-aligned
#define BUF_P      12288                       // per buffer: 3 arr * 32 st * 32 ln * 4
#define BUF_ARR    4096
#define SMEM_TOTAL (BUF_OFF + 2 * BUF_P)       // 58496

extern __shared__ char smem_raw[];

__device__ __forceinline__ uint32_t smem_u32(const void* p) {
    uint32_t a;
    asm("{ .reg .u64 t; cvta.to.shared.u64 t, %1; cvt.u32.u64 %0, t; }"
        : "=r"(a) : "l"(p));
    return a;
}
__device__ __forceinline__ void sts128(uint32_t a, float x, float y, float z, float w) {
    asm volatile("st.shared.v4.f32 [%0], {%1, %2, %3, %4};"
                 :: "r"(a), "f"(x), "f"(y), "f"(z), "f"(w) : "memory");
}
__device__ __forceinline__ float4 lds128(uint32_t a) {
    float4 v;
    asm volatile("ld.shared.v4.f32 {%0, %1, %2, %3}, [%4];"
                 : "=f"(v.x), "=f"(v.y), "=f"(v.z), "=f"(v.w) : "r"(a));
    return v;
}
#define BAR_SYNC(id)   asm volatile("bar.sync %0, 64;"   :: "r"(id) : "memory")
#define BAR_ARRIVE(id) asm volatile("bar.arrive %0, 64;" :: "r"(id) : "memory")

// exact reference increment: (((0.14f*(0.1f*t))*0.125f)*0.1f)
__device__ __forceinline__ float q_inc(float tf) {
    return __fmul_rn(__fmul_rn(__fmul_rn(SIGMA_C, __fmul_rn(DT_C, tf)),
                               0.125f), DT_C);
}

__global__ void __launch_bounds__(64, 1)
simulate_kernel(const float* __restrict__ Cv, const float* __restrict__ Kp,
                const float* __restrict__ jminp, float* __restrict__ out) {
    const int tid  = threadIdx.x;
    const int lane = tid & 31;
    const int wid  = tid >> 5;
    const float MAGIC = 12582912.0f;    // 1.5 * 2^23

    float2* s_tab = reinterpret_cast<float2*>(smem_raw);
    float*  sQ    = reinterpret_cast<float*>(smem_raw + Q_OFF);

    // cooperative tab build straight from g_nodes (both warps)
    {
        const int k0 = tid * (TABN / 64);
        float nm = __ldg(g_nodes + k0);
        float nc = __ldg(g_nodes + k0 + 1);
#pragma unroll 8
        for (int k = k0; k < k0 + TABN / 64; ++k) {
            const float np = __ldg(g_nodes + k + 2);
            const float slope = 0.5f * (np - nm);
            s_tab[k] = make_float2(fmaf(-slope, (float)k, nc), slope * INVH_F);
            nm = nc; nc = np;
        }
    }
    __syncthreads();

    const uint32_t tab32 = smem_u32(s_tab);
    const uint32_t buf32 = smem_u32(smem_raw + BUF_OFF);

    const int e = blockIdx.x * 32 + lane;
    float* oth = out + (size_t)e * NT_C;
    float* ore = oth + (size_t)B_C * NT_C;
    float* ocu = ore + (size_t)B_C * NT_C;
    float* oti = ocu + (size_t)B_C * NT_C;

    if (wid == 1) {
        // =================== writer warp ===================
        BAR_ARRIVE(3);                        // prime free barriers
        BAR_ARRIVE(4);
        // frozen region [0, 112): closed form, independent of Q/t*
#pragma unroll 4
        for (int q = 0; q < T_FROZEN / 4; ++q) {
            const float t0 = (float)(4 * q);
            float j0 = __fmul_rn(t0, 0.00175f);
            if (q == 0) j0 = 1e-3f;
            const int b4 = 4 * q;
            *reinterpret_cast<float4*>(oth + b4) = make_float4(0.f, 0.f, 0.f, 0.f);
            *reinterpret_cast<float4*>(ore + b4) = make_float4(R0_C, R0_C, R0_C, R0_C);
            *reinterpret_cast<float4*>(ocu + b4) =
                make_float4(j0,
                            __fmul_rn(t0 + 1.0f, 0.00175f),
                            __fmul_rn(t0 + 2.0f, 0.00175f),
                            __fmul_rn(t0 + 3.0f, 0.00175f));
            *reinterpret_cast<float4*>(oti + b4) =
                make_float4(__fmul_rn(DT_C, t0),
                            __fmul_rn(DT_C, t0 + 1.0f),
                            __fmul_rn(DT_C, t0 + 2.0f),
                            __fmul_rn(DT_C, t0 + 3.0f));
        }
        const uint32_t lb = buf32 + lane * 16;
        for (int tile = 0; tile < NTILES_A; ++tile) {
            const int p = tile & 1;
            BAR_SYNC(1 + p);                  // wait buffer ready
            const uint32_t bp = lb + p * BUF_P;
            const int base = T_FROZEN + tile * TILE_S;
            const float tfb = (float)base;
#pragma unroll
            for (int q = 0; q < TILE_S / 4; ++q) {
                const float4 a = lds128(bp + 0 * BUF_ARR + q * 512);
                const float4 b = lds128(bp + 1 * BUF_ARR + q * 512);
                const float4 c = lds128(bp + 2 * BUF_ARR + q * 512);
                *reinterpret_cast<float4*>(oth + base + 4 * q) = a;
                *reinterpret_cast<float4*>(ore + base + 4 * q) = b;
                *reinterpret_cast<float4*>(ocu + base + 4 * q) = c;
                const float tq = tfb + (float)(4 * q);
                *reinterpret_cast<float4*>(oti + base + 4 * q) =
                    make_float4(__fmul_rn(DT_C, tq),
                                __fmul_rn(DT_C, tq + 1.0f),
                                __fmul_rn(DT_C, tq + 2.0f),
                                __fmul_rn(DT_C, tq + 3.0f));
            }
            BAR_ARRIVE(3 + p);                // buffer free
        }
        return;
    }

    // =================== compute warp ===================
    // exact serial Q prefix (all lanes redundantly; lane 0 stores)
    {
        float Q = 0.0f;
        if (lane == 0) sQ[0] = 0.0f;
        for (int t = 1; t < QLEN; t += 4) {
            const float f0 = (float)t;
            const float i0 = q_inc(f0);
            const float i1 = q_inc(f0 + 1.0f);
            const float i2 = q_inc(f0 + 2.0f);
            const float i3 = q_inc(f0 + 3.0f);
            Q = __fadd_rn(Q, i0); if (lane == 0) sQ[t]     = Q;
            Q = __fadd_rn(Q, i1); if (lane == 0) sQ[t + 1] = Q;
            Q = __fadd_rn(Q, i2); if (lane == 0) sQ[t + 2] = Q;
            Q = __fadd_rn(Q, i3); if (lane == 0) sQ[t + 3] = Q;
        }
    }
    __syncwarp();

    const float cv  = __ldg(Cv + e);
    const float kk  = __ldg(Kp + e);
    const float jmn = __ldg(jminp + e);

    const double beta_d = 0.14 * 1.0 / (0.14 * 50.0 + 1.0);
    const float CQ = (float)pow(81.0 / (128.0 * beta_d), 1.0 / 3.0);
    const float Qmin = CQ * powf(kk, 4.0f / 3.0f);     // in [1.31, 5.69)

    // t* = first t with Q_t > Qmin  (t* in [113, 257))
    int lo = 0, hi = QLEN;
    while (hi - lo > 1) {
        const int mid = (lo + hi) >> 1;
        if (sQ[mid] <= Qmin) lo = mid; else hi = mid;
    }
    const int tstar = hi;
    const int tmax  = __reduce_max_sync(0xFFFFFFFFu, tstar);

    int steadyTile = (tmax + 2 - T_FROZEN + TILE_S - 1) / TILE_S;
    if (steadyTile > NTILES_A) steadyTile = NTILES_A;

    float res = R0_C, thk = 0.0f;
    const float cvdt = __fmul_rn(cv, DT_C);
    const float mjcC = __fmul_rn(-jmn, cvdt);

    // pipeline init at t0 = 112 (all lanes frozen through >= 113)
    float u = 0.125f;                                   // exact 1/8
    const float nuA = __fmul_rn(__fmul_rn(112.0f, 0.014f), 0.125f);
    const float nuB = __fmul_rn(__fmul_rn(113.0f, 0.014f), 0.125f);
    float p0 = __fmul_rn(nuA, 0.125f), q0 = __fmul_rn(nuA, 2.0f);
    float p1 = __fmul_rn(nuB, 0.125f), q1 = __fmul_rn(nuB, 2.0f);
    float c00, c10;  float2 te1, te_raw;
#pragma unroll
    for (int k = 0; k < 3; ++k) {
        const float jk = __fmul_rn(112.0f + (float)k, 0.00175f);
        const float m  = fmaf(jk, INVH_F, MAGIC);
        uint32_t iu = __float_as_uint(m) & 0x3FFFFFu;
        iu = min(iu, (uint32_t)(TABN - 1));
        const float2 te = s_tab[iu];
        if (k == 0)      { c00 = te.x; c10 = te.y; }
        else if (k == 1) te1 = te;
        else             te_raw = te;
    }
    float cvde0 = 0.0f, mjc0 = 0.0f;                    // t=112 < t*
    float cvde1 = 0.0f, mjc1 = 0.0f;                    // t=113 < t*
    float tcp = 114.0f;                                 // t being prepped

    const uint32_t sb = buf32 + lane * 16;
    float sth[4], sre[4], scu[4];

    int tile = 0;
    // -------- transition tiles (per-step gate) --------
    for (; tile < steadyTile; ++tile) {
        const int p = tile & 1;
        BAR_SYNC(3 + p);
        const uint32_t bp = sb + p * BUF_P;
        const int base = T_FROZEN + tile * TILE_S;
#pragma unroll
        for (int s = 0; s < TILE_S; ++s) {
            const float resin = res;
            // ---------------- critical chain (20 cyc) ----------------
            const float den = fmaf(resin, SIGMA_C, 1.0f);
            const float jv  = fmaf(den, -p0, q0);        // num/den, Newton-folded
            const float rho = fmaf(jv, c10, c00);
            const float jd  = fmaf(jv, cvde0, mjc0);     // frozen: exactly 0
            const float rc  = fmaf(rho, jd, resin);
            res = fmaxf(rc, R0_C);
            thk = fmaxf(thk + jd, 0.0f);
            sth[s & 3] = thk; sre[s & 3] = res; scu[s & 3] = jv;
            // ---------------- prep step t+2 (off-chain) ----------------
            const float tN  = fmaf(den, -u, 2.0f);       // self-Newton on u
            const float u2  = __fmul_rn(u, tN);
            u = u2;
            const float num2 = __fmul_rn(tcp, 0.014f);
            const float nu2  = __fmul_rn(num2, u2);
            const float p2   = __fmul_rn(nu2, u2);
            const float q2   = __fmul_rn(nu2, 2.0f);
            const float m    = fmaf(nu2, INVH_F, MAGIC); // nu2 == predicted j
            uint32_t iu = __float_as_uint(m) & 0x3FFFFFu;
            iu = min(iu, (uint32_t)(TABN - 1));
            float na, nb;
            asm volatile("ld.shared.v2.f32 {%0, %1}, [%2];"
                         : "=f"(na), "=f"(nb) : "r"(tab32 + iu * 8u));
            const bool a2 = (base + s + 2 >= tstar);
            const float cd2 = a2 ? cvdt : 0.0f;
            const float mj2 = a2 ? mjcC : 0.0f;
            // rotate (renamed by unroll)
            p0 = p1; q0 = q1;
            c00 = te1.x; c10 = te1.y;
            cvde0 = cvde1; mjc0 = mjc1;
            p1 = p2; q1 = q2;
            te1 = te_raw; te_raw.x = na; te_raw.y = nb;
            cvde1 = cd2;  mjc1 = mj2;
            tcp += 1.0f;
            if ((s & 3) == 3) {
                const uint32_t qo = (uint32_t)(s >> 2) * 512u;
                sts128(bp + 0 * BUF_ARR + qo, sth[0], sth[1], sth[2], sth[3]);
                sts128(bp + 1 * BUF_ARR + qo, sre[0], sre[1], sre[2], sre[3]);
                sts128(bp + 2 * BUF_ARR + qo, scu[0], scu[1], scu[2], scu[3]);
            }
        }
        BAR_ARRIVE(1 + p);
    }
    // -------- steady tiles (gate constant) --------
    for (; tile < NTILES_A; ++tile) {
        const int p = tile & 1;
        BAR_SYNC(3 + p);
        const uint32_t bp = sb + p * BUF_P;
#pragma unroll
        for (int s = 0; s < TILE_S; ++s) {
            const float resin = res;
            const float den = fmaf(resin, SIGMA_C, 1.0f);
            const float jv  = fmaf(den, -p0, q0);
            const float rho = fmaf(jv, c10, c00);
            const float jd  = fmaf(jv, cvdt, mjcC);
            const float rc  = fmaf(rho, jd, resin);
            res = fmaxf(rc, R0_C);
            thk = fmaxf(thk + jd, 0.0f);
            sth[s & 3] = thk; sre[s & 3] = res; scu[s & 3] = jv;
            // prep t+2
            const float tN  = fmaf(den, -u, 2.0f);
            const float u2  = __fmul_rn(u, tN);
            u = u2;
            const float num2 = __fmul_rn(tcp, 0.014f);
            const float nu2  = __fmul_rn(num2, u2);
            const float p2   = __fmul_rn(nu2, u2);
            const float q2   = __fmul_rn(nu2, 2.0f);
            const float m    = fmaf(nu2, INVH_F, MAGIC);
            uint32_t iu = __float_as_uint(m) & 0x3FFFFFu;
            iu = min(iu, (uint32_t)(TABN - 1));
            float na, nb;
            asm volatile("ld.shared.v2.f32 {%0, %1}, [%2];"
                         : "=f"(na), "=f"(nb) : "r"(tab32 + iu * 8u));
            // rotate
            p0 = p1; q0 = q1;
            c00 = te1.x; c10 = te1.y;
            p1 = p2; q1 = q2;
            te1 = te_raw; te_raw.x = na; te_raw.y = nb;
            tcp += 1.0f;
            if ((s & 3) == 3) {
                const uint32_t qo = (uint32_t)(s >> 2) * 512u;
                sts128(bp + 0 * BUF_ARR + qo, sth[0], sth[1], sth[2], sth[3]);
                sts128(bp + 1 * BUF_ARR + qo, sre[0], sre[1], sre[2], sre[3]);
                sts128(bp + 2 * BUF_ARR + qo, scu[0], scu[1], scu[2], scu[3]);
            }
        }
        BAR_ARRIVE(1 + p);
    }
}

// ---------------------------------------------------------------------------
// Inputs: Cv, K, jmin, W1, b1, W2, b2, W3, b3
// Output: concat(thickness, resistance, current, time), each (B, NT).
// ---------------------------------------------------------------------------
extern "C" void kernel_launch(void* const* d_in, const int* in_sizes, int n_in,
                              void* d_out, int out_size) {
    const float* Cv = (const float*)d_in[0];
    const float* K  = (const float*)d_in[1];
    const float* jm = (const float*)d_in[2];
    const float* W1 = (const float*)d_in[3];
    const float* b1 = (const float*)d_in[4];
    const float* W2 = (const float*)d_in[5];
    const float* b2 = (const float*)d_in[6];
    const float* W3 = (const float*)d_in[7];
    const float* b3 = (const float*)d_in[8];
    float* out = (float*)d_out;

    build_nodes_kernel<<<NODE_BLOCKS, 128>>>(W1, b1, W2, b2, W3, b3);

    cudaFuncSetAttribute(simulate_kernel,
                         cudaFuncAttributeMaxDynamicSharedMemorySize, SMEM_TOTAL);
    simulate_kernel<<<B_C / 32, 64, SMEM_TOTAL>>>(Cv, K, jm, out);
}

// round 10
// speedup vs baseline: 3.6988x; 1.2290x over previous
#include <cuda_runtime.h>
#include <cstdint>
#include <math.h>

// ---------------- problem constants ----------------
#define SIGMA_C 0.14f
#define L_C     1.0f
#define R0_C    50.0f
#define DT_C    0.1f
#define NT_C    2000
#define B_C     4096

// rho(j) table: j in [0, 3.5]; res >= 50 invariant => j <= 3.49825
#define TABN   4096
#define NNODES (TABN + 2)
#define JMAX_C 3.5f
#define INVH_F ((float)TABN / JMAX_C)

// frozen prefix: K >= 0.5 -> Qmin >= 1.311 > Q(112) = 1.107  => t* >= 113
#define T_FROZEN 112
#define TILE_S   32
#define NTILES_A ((NT_C - T_FROZEN) / TILE_S)    // 59
// Q prefix needed only to t <= 256 (Qmin < 5.69; Q(256) = 5.757)
#define QLEN 272

__device__ float g_nodes[NNODES];

// ---------------------------------------------------------------------------
// build_nodes: exact fp32 MLP rho(x) at table nodes. 4 threads/node, 16 units
// each, W2 in SMEM, sh1 padded to kill bank conflicts.
// ---------------------------------------------------------------------------
#define NODE_BLOCKS ((NNODES + 31) / 32)      // 129

__global__ void __launch_bounds__(128)
build_nodes_kernel(const float* __restrict__ W1, const float* __restrict__ b1,
                   const float* __restrict__ W2, const float* __restrict__ b2,
                   const float* __restrict__ W3, const float* __restrict__ b3) {
    const int tid = threadIdx.x;
    __shared__ float sW2[64 * 64];
    __shared__ float sh1[32][65];
    {
        const float4* src = reinterpret_cast<const float4*>(W2);
        float4* dst = reinterpret_cast<float4*>(sW2);
#pragma unroll
        for (int q = 0; q < 8; ++q) dst[tid + 128 * q] = __ldg(src + tid + 128 * q);
    }

    const int nl = tid >> 2;
    const int c  = tid & 3;
    const int node = blockIdx.x * 32 + nl;
    const float H = JMAX_C / (float)TABN;
    const float x = (float)(node - 1) * H;

#pragma unroll
    for (int k = 0; k < 16; ++k) {
        const int u = c * 16 + k;
        sh1[nl][u] = fmaxf(fmaf(x, __ldg(W1 + u), __ldg(b1 + u)), 0.0f);
    }
    __syncthreads();

    float acc[16];
#pragma unroll
    for (int k = 0; k < 16; ++k) acc[k] = __ldg(b2 + c * 16 + k);
#pragma unroll 4
    for (int j = 0; j < 64; ++j) {
        const float hj = sh1[nl][j];
        const float4* row = reinterpret_cast<const float4*>(sW2 + j * 64 + c * 16);
#pragma unroll
        for (int q = 0; q < 4; ++q) {
            const float4 w = row[q];
            acc[q * 4 + 0] = fmaf(hj, w.x, acc[q * 4 + 0]);
            acc[q * 4 + 1] = fmaf(hj, w.y, acc[q * 4 + 1]);
            acc[q * 4 + 2] = fmaf(hj, w.z, acc[q * 4 + 2]);
            acc[q * 4 + 3] = fmaf(hj, w.w, acc[q * 4 + 3]);
        }
    }
    float part = 0.0f;
#pragma unroll
    for (int k = 0; k < 16; ++k)
        part = fmaf(fmaxf(acc[k], 0.0f), __ldg(W3 + c * 16 + k), part);
    part += __shfl_down_sync(0xFFFFFFFFu, part, 2);
    part += __shfl_down_sync(0xFFFFFFFFu, part, 1);
    if (c == 0 && node < NNODES) g_nodes[node] = part + __ldg(b3);
}

// ---------------------------------------------------------------------------
// simulate: 64 threads/CTA. Warp 0 computes; warp 1 drains double-buffered
// SMEM tiles to GMEM with fully COALESCED stores.
// SMEM tile layout (per array): 32 element-rows x 128B (32 steps), with XOR
// swizzle chunk' = chunk ^ (el&7):
//   - compute STS.128 (lane = el): phases hit 8 distinct columns, no conflict
//   - writer LDS.128 (4 els/instr, lane&7 = chunk): conflict-free
//   - writer STG.128: 4 fully-covered 128B lines (4 wavefronts, not 32)
// Per-step chain (20 cyc): den -> j = fma(den,-p,q) -> {rho,jd} -> rc -> max.
// ---------------------------------------------------------------------------
#define TAB_BYTES  (TABN * 8)                  // 32768
#define Q_OFF      TAB_BYTES                   // float[QLEN]
#define BUF_OFF    33920                       // 128-aligned
#define BUF_ARR    4096                        // 32 rows * 128B
#define BUF_P      (3 * BUF_ARR)               // 12288
#define SMEM_TOTAL (BUF_OFF + 2 * BUF_P)       // 58496

extern __shared__ char smem_raw[];

__device__ __forceinline__ uint32_t smem_u32(const void* p) {
    uint32_t a;
    asm("{ .reg .u64 t; cvta.to.shared.u64 t, %1; cvt.u32.u64 %0, t; }"
        : "=r"(a) : "l"(p));
    return a;
}
__device__ __forceinline__ void sts128(uint32_t a, float x, float y, float z, float w) {
    asm volatile("st.shared.v4.f32 [%0], {%1, %2, %3, %4};"
                 :: "r"(a), "f"(x), "f"(y), "f"(z), "f"(w) : "memory");
}
__device__ __forceinline__ float4 lds128(uint32_t a) {
    float4 v;
    asm volatile("ld.shared.v4.f32 {%0, %1, %2, %3}, [%4];"
                 : "=f"(v.x), "=f"(v.y), "=f"(v.z), "=f"(v.w) : "r"(a));
    return v;
}
#define BAR_SYNC(id)   asm volatile("bar.sync %0, 64;"   :: "r"(id) : "memory")
#define BAR_ARRIVE(id) asm volatile("bar.arrive %0, 64;" :: "r"(id) : "memory")

// exact reference increment: (((0.14f*(0.1f*t))*0.125f)*0.1f)
__device__ __forceinline__ float q_inc(float tf) {
    return __fmul_rn(__fmul_rn(__fmul_rn(SIGMA_C, __fmul_rn(DT_C, tf)),
                               0.125f), DT_C);
}

__global__ void __launch_bounds__(64, 1)
simulate_kernel(const float* __restrict__ Cv, const float* __restrict__ Kp,
                const float* __restrict__ jminp, float* __restrict__ out) {
    const int tid  = threadIdx.x;
    const int lane = tid & 31;
    const int wid  = tid >> 5;
    const float MAGIC = 12582912.0f;    // 1.5 * 2^23

    float2* s_tab = reinterpret_cast<float2*>(smem_raw);
    float*  sQ    = reinterpret_cast<float*>(smem_raw + Q_OFF);

    // cooperative tab build straight from g_nodes (both warps)
    {
        const int k0 = tid * (TABN / 64);
        float nm = __ldg(g_nodes + k0);
        float nc = __ldg(g_nodes + k0 + 1);
#pragma unroll 8
        for (int k = k0; k < k0 + TABN / 64; ++k) {
            const float np = __ldg(g_nodes + k + 2);
            const float slope = 0.5f * (np - nm);
            s_tab[k] = make_float2(fmaf(-slope, (float)k, nc), slope * INVH_F);
            nm = nc; nc = np;
        }
    }
    __syncthreads();

    const uint32_t tab32 = smem_u32(s_tab);
    const uint32_t buf32 = smem_u32(smem_raw + BUF_OFF);
    const int e0 = blockIdx.x * 32;

    if (wid == 1) {
        // =================== writer warp (all coalesced) ===================
        BAR_ARRIVE(3);                        // prime free barriers
        BAR_ARRIVE(4);

        float* oth0 = out + (size_t)e0 * NT_C;
        float* ore0 = oth0 + (size_t)B_C * NT_C;
        float* ocu0 = ore0 + (size_t)B_C * NT_C;
        float* oti0 = ocu0 + (size_t)B_C * NT_C;

        const int elw = lane >> 3;            // element within group of 4
        const int ch  = lane & 7;             // 16B chunk within 128B row-seg

        // frozen region [0, 112): values depend only on t; coalesced STG.128
        // 28 chunks of 4 steps; lane covers chunks ch, ch+8, ch+16, ch+24
#pragma unroll
        for (int eg = 0; eg < 8; ++eg) {
            const int el = eg * 4 + elw;
            const size_t ro = (size_t)el * NT_C;
#pragma unroll
            for (int cc = 0; cc < 4; ++cc) {
                const int chunk = cc * 8 + ch;
                if (chunk < T_FROZEN / 4) {
                    const int t0 = chunk * 4;
                    const float tf = (float)t0;
                    float j0 = __fmul_rn(tf, 0.00175f);
                    if (t0 == 0) j0 = 1e-3f;
                    *reinterpret_cast<float4*>(oth0 + ro + t0) =
                        make_float4(0.f, 0.f, 0.f, 0.f);
                    *reinterpret_cast<float4*>(ore0 + ro + t0) =
                        make_float4(R0_C, R0_C, R0_C, R0_C);
                    *reinterpret_cast<float4*>(ocu0 + ro + t0) =
                        make_float4(j0,
                                    __fmul_rn(tf + 1.0f, 0.00175f),
                                    __fmul_rn(tf + 2.0f, 0.00175f),
                                    __fmul_rn(tf + 3.0f, 0.00175f));
                    *reinterpret_cast<float4*>(oti0 + ro + t0) =
                        make_float4(__fmul_rn(DT_C, tf),
                                    __fmul_rn(DT_C, tf + 1.0f),
                                    __fmul_rn(DT_C, tf + 2.0f),
                                    __fmul_rn(DT_C, tf + 3.0f));
                }
            }
        }

        for (int tile = 0; tile < NTILES_A; ++tile) {
            const int p = tile & 1;
            BAR_SYNC(1 + p);                  // wait buffer ready
            const uint32_t bp = buf32 + p * BUF_P;
            const int base = T_FROZEN + tile * TILE_S;
            const float tq0 = (float)(base + ch * 4);
            const float4 tv = make_float4(__fmul_rn(DT_C, tq0),
                                          __fmul_rn(DT_C, tq0 + 1.0f),
                                          __fmul_rn(DT_C, tq0 + 2.0f),
                                          __fmul_rn(DT_C, tq0 + 3.0f));
#pragma unroll
            for (int eg = 0; eg < 8; ++eg) {
                const int el = eg * 4 + elw;
                const uint32_t sa = bp + (uint32_t)el * 128u
                                  + (uint32_t)((ch ^ (el & 7)) << 4);
                const float4 a = lds128(sa + 0 * BUF_ARR);
                const float4 b = lds128(sa + 1 * BUF_ARR);
                const float4 c = lds128(sa + 2 * BUF_ARR);
                const size_t go = (size_t)el * NT_C + base + ch * 4;
                *reinterpret_cast<float4*>(oth0 + go) = a;
                *reinterpret_cast<float4*>(ore0 + go) = b;
                *reinterpret_cast<float4*>(ocu0 + go) = c;
                *reinterpret_cast<float4*>(oti0 + go) = tv;
            }
            BAR_ARRIVE(3 + p);                // buffer free
        }
        return;
    }

    // =================== compute warp ===================
    // exact serial Q prefix (all lanes redundantly; lane 0 stores)
    {
        float Q = 0.0f;
        if (lane == 0) sQ[0] = 0.0f;
        for (int t = 1; t < QLEN; t += 4) {
            const float f0 = (float)t;
            const float i0 = q_inc(f0);
            const float i1 = q_inc(f0 + 1.0f);
            const float i2 = q_inc(f0 + 2.0f);
            const float i3 = q_inc(f0 + 3.0f);
            Q = __fadd_rn(Q, i0); if (lane == 0) sQ[t]     = Q;
            Q = __fadd_rn(Q, i1); if (lane == 0) sQ[t + 1] = Q;
            Q = __fadd_rn(Q, i2); if (lane == 0) sQ[t + 2] = Q;
            Q = __fadd_rn(Q, i3); if (lane == 0) sQ[t + 3] = Q;
        }
    }
    __syncwarp();

    const int e = e0 + lane;
    const float cv  = __ldg(Cv + e);
    const float kk  = __ldg(Kp + e);
    const float jmn = __ldg(jminp + e);

    const double beta_d = 0.14 * 1.0 / (0.14 * 50.0 + 1.0);
    const float CQ = (float)pow(81.0 / (128.0 * beta_d), 1.0 / 3.0);
    const float Qmin = CQ * powf(kk, 4.0f / 3.0f);     // in [1.31, 5.69)

    // t* = first t with Q_t > Qmin  (t* in [113, 257))
    int lo = 0, hi = QLEN;
    while (hi - lo > 1) {
        const int mid = (lo + hi) >> 1;
        if (sQ[mid] <= Qmin) lo = mid; else hi = mid;
    }
    const int tstar = hi;
    const int tmax  = __reduce_max_sync(0xFFFFFFFFu, tstar);

    int steadyTile = (tmax + 2 - T_FROZEN + TILE_S - 1) / TILE_S;
    if (steadyTile > NTILES_A) steadyTile = NTILES_A;

    float res = R0_C, thk = 0.0f;
    const float cvdt = __fmul_rn(cv, DT_C);
    const float mjcC = __fmul_rn(-jmn, cvdt);

    // pipeline init at t0 = 112 (all lanes frozen through >= 113)
    float u = 0.125f;                                   // exact 1/8
    const float nuA = __fmul_rn(__fmul_rn(112.0f, 0.014f), 0.125f);
    const float nuB = __fmul_rn(__fmul_rn(113.0f, 0.014f), 0.125f);
    float p0 = __fmul_rn(nuA, 0.125f), q0 = __fmul_rn(nuA, 2.0f);
    float p1 = __fmul_rn(nuB, 0.125f), q1 = __fmul_rn(nuB, 2.0f);
    float c00, c10;  float2 te1, te_raw;
#pragma unroll
    for (int k = 0; k < 3; ++k) {
        const float jk = __fmul_rn(112.0f + (float)k, 0.00175f);
        const float m  = fmaf(jk, INVH_F, MAGIC);
        uint32_t iu = __float_as_uint(m) & 0x3FFFFFu;
        iu = min(iu, (uint32_t)(TABN - 1));
        const float2 te = s_tab[iu];
        if (k == 0)      { c00 = te.x; c10 = te.y; }
        else if (k == 1) te1 = te;
        else             te_raw = te;
    }
    float cvde0 = 0.0f, mjc0 = 0.0f;                    // t=112 < t*
    float cvde1 = 0.0f, mjc1 = 0.0f;                    // t=113 < t*
    float tcp = 114.0f;                                 // t being prepped

    // swizzled row base for this lane's element
    const uint32_t row_l = buf32 + (uint32_t)lane * 128u;
    const uint32_t sw_l  = (uint32_t)((lane & 7) << 4);
    float sth[4], sre[4], scu[4];

    int tile = 0;
    // -------- transition tiles (per-step gate) --------
    for (; tile < steadyTile; ++tile) {
        const int p = tile & 1;
        BAR_SYNC(3 + p);
        const uint32_t bp = row_l + p * BUF_P;
        const int base = T_FROZEN + tile * TILE_S;
#pragma unroll
        for (int s = 0; s < TILE_S; ++s) {
            const float resin = res;
            // ---------------- critical chain (20 cyc) ----------------
            const float den = fmaf(resin, SIGMA_C, 1.0f);
            const float jv  = fmaf(den, -p0, q0);        // num/den, Newton-folded
            const float rho = fmaf(jv, c10, c00);
            const float jd  = fmaf(jv, cvde0, mjc0);     // frozen: exactly 0
            const float rc  = fmaf(rho, jd, resin);
            res = fmaxf(rc, R0_C);
            thk = fmaxf(thk + jd, 0.0f);
            sth[s & 3] = thk; sre[s & 3] = res; scu[s & 3] = jv;
            // ---------------- prep step t+2 (off-chain) ----------------
            const float tN  = fmaf(den, -u, 2.0f);       // self-Newton on u
            const float u2  = __fmul_rn(u, tN);
            u = u2;
            const float num2 = __fmul_rn(tcp, 0.014f);
            const float nu2  = __fmul_rn(num2, u2);
            const float p2   = __fmul_rn(nu2, u2);
            const float q2   = __fmul_rn(nu2, 2.0f);
            const float m    = fmaf(nu2, INVH_F, MAGIC); // nu2 == predicted j
            uint32_t iu = __float_as_uint(m) & 0x3FFFFFu;
            iu = min(iu, (uint32_t)(TABN - 1));
            float na, nb;
            asm volatile("ld.shared.v2.f32 {%0, %1}, [%2];"
                         : "=f"(na), "=f"(nb) : "r"(tab32 + iu * 8u));
            const bool a2 = (base + s + 2 >= tstar);
            const float cd2 = a2 ? cvdt : 0.0f;
            const float mj2 = a2 ? mjcC : 0.0f;
            // rotate (renamed by unroll)
            p0 = p1; q0 = q1;
            c00 = te1.x; c10 = te1.y;
            cvde0 = cvde1; mjc0 = mjc1;
            p1 = p2; q1 = q2;
            te1 = te_raw; te_raw.x = na; te_raw.y = nb;
            cvde1 = cd2;  mjc1 = mj2;
            tcp += 1.0f;
            if ((s & 3) == 3) {
                const uint32_t co = (uint32_t)(((s >> 2) << 4)) ^ sw_l;
                sts128(bp + 0 * BUF_ARR + co, sth[0], sth[1], sth[2], sth[3]);
                sts128(bp + 1 * BUF_ARR + co, sre[0], sre[1], sre[2], sre[3]);
                sts128(bp + 2 * BUF_ARR + co, scu[0], scu[1], scu[2], scu[3]);
            }
        }
        BAR_ARRIVE(1 + p);
    }
    // -------- steady tiles (gate constant) --------
    for (; tile < NTILES_A; ++tile) {
        const int p = tile & 1;
        BAR_SYNC(3 + p);
        const uint32_t bp = row_l + p * BUF_P;
#pragma unroll
        for (int s = 0; s < TILE_S; ++s) {
            const float resin = res;
            const float den = fmaf(resin, SIGMA_C, 1.0f);
            const float jv  = fmaf(den, -p0, q0);
            const float rho = fmaf(jv, c10, c00);
            const float jd  = fmaf(jv, cvdt, mjcC);
            const float rc  = fmaf(rho, jd, resin);
            res = fmaxf(rc, R0_C);
            thk = fmaxf(thk + jd, 0.0f);
            sth[s & 3] = thk; sre[s & 3] = res; scu[s & 3] = jv;
            // prep t+2
            const float tN  = fmaf(den, -u, 2.0f);
            const float u2  = __fmul_rn(u, tN);
            u = u2;
            const float num2 = __fmul_rn(tcp, 0.014f);
            const float nu2  = __fmul_rn(num2, u2);
            const float p2   = __fmul_rn(nu2, u2);
            const float q2   = __fmul_rn(nu2, 2.0f);
            const float m    = fmaf(nu2, INVH_F, MAGIC);
            uint32_t iu = __float_as_uint(m) & 0x3FFFFFu;
            iu = min(iu, (uint32_t)(TABN - 1));
            float na, nb;
            asm volatile("ld.shared.v2.f32 {%0, %1}, [%2];"
                         : "=f"(na), "=f"(nb) : "r"(tab32 + iu * 8u));
            // rotate
            p0 = p1; q0 = q1;
            c00 = te1.x; c10 = te1.y;
            p1 = p2; q1 = q2;
            te1 = te_raw; te_raw.x = na; te_raw.y = nb;
            tcp += 1.0f;
            if ((s & 3) == 3) {
                const uint32_t co = (uint32_t)(((s >> 2) << 4)) ^ sw_l;
                sts128(bp + 0 * BUF_ARR + co, sth[0], sth[1], sth[2], sth[3]);
                sts128(bp + 1 * BUF_ARR + co, sre[0], sre[1], sre[2], sre[3]);
                sts128(bp + 2 * BUF_ARR + co, scu[0], scu[1], scu[2], scu[3]);
            }
        }
        BAR_ARRIVE(1 + p);
    }
}

// ---------------------------------------------------------------------------
// Inputs: Cv, K, jmin, W1, b1, W2, b2, W3, b3
// Output: concat(thickness, resistance, current, time), each (B, NT).
// ---------------------------------------------------------------------------
extern "C" void kernel_launch(void* const* d_in, const int* in_sizes, int n_in,
                              void* d_out, int out_size) {
    const float* Cv = (const float*)d_in[0];
    const float* K  = (const float*)d_in[1];
    const float* jm = (const float*)d_in[2];
    const float* W1 = (const float*)d_in[3];
    const float* b1 = (const float*)d_in[4];
    const float* W2 = (const float*)d_in[5];
    const float* b2 = (const float*)d_in[6];
    const float* W3 = (const float*)d_in[7];
    const float* b3 = (const float*)d_in[8];
    float* out = (float*)d_out;

    build_nodes_kernel<<<NODE_BLOCKS, 128>>>(W1, b1, W2, b2, W3, b3);

    cudaFuncSetAttribute(simulate_kernel,
                         cudaFuncAttributeMaxDynamicSharedMemorySize, SMEM_TOTAL);
    simulate_kernel<<<B_C / 32, 64, SMEM_TOTAL>>>(Cv, K, jm, out);
}

// round 11
// speedup vs baseline: 3.7432x; 1.0120x over previous
#include <cuda_runtime.h>
#include <cstdint>
#include <math.h>

// ---------------- problem constants ----------------
#define SIGMA_C 0.14f
#define L_C     1.0f
#define R0_C    50.0f
#define DT_C    0.1f
#define NT_C    2000
#define B_C     4096

// rho(j) table: j in [0, 3.5]; res >= 50 invariant => j <= 3.49825
#define TABN   1024
#define NNODES (TABN + 2)
#define JMAX_C 3.5f
#define INVH_F ((float)TABN / JMAX_C)

// frozen prefix: K >= 0.5 -> Qmin >= 1.311 > Q(112) = 1.107  => t* >= 113
#define T_FROZEN 112
#define TILE_S   32
#define NTILES_A ((NT_C - T_FROZEN) / TILE_S)    // 59
// Q prefix needed only to t <= 256 (Qmin < 5.69; Q(256) = 5.757)
#define QLEN 272

__device__ float g_nodes[NNODES];

// ---------------------------------------------------------------------------
// build_nodes: exact fp32 MLP rho(x) at table nodes. 4 threads/node, 16 units
// each, W2 in SMEM, sh1 padded to kill bank conflicts.
// ---------------------------------------------------------------------------
#define NODE_BLOCKS ((NNODES + 31) / 32)      // 33

__global__ void __launch_bounds__(128)
build_nodes_kernel(const float* __restrict__ W1, const float* __restrict__ b1,
                   const float* __restrict__ W2, const float* __restrict__ b2,
                   const float* __restrict__ W3, const float* __restrict__ b3) {
    const int tid = threadIdx.x;
    __shared__ float sW2[64 * 64];
    __shared__ float sh1[32][65];
    {
        const float4* src = reinterpret_cast<const float4*>(W2);
        float4* dst = reinterpret_cast<float4*>(sW2);
#pragma unroll
        for (int q = 0; q < 8; ++q) dst[tid + 128 * q] = __ldg(src + tid + 128 * q);
    }

    const int nl = tid >> 2;
    const int c  = tid & 3;
    const int node = blockIdx.x * 32 + nl;
    const float H = JMAX_C / (float)TABN;
    const float x = (float)(node - 1) * H;

#pragma unroll
    for (int k = 0; k < 16; ++k) {
        const int u = c * 16 + k;
        sh1[nl][u] = fmaxf(fmaf(x, __ldg(W1 + u), __ldg(b1 + u)), 0.0f);
    }
    __syncthreads();

    float acc[16];
#pragma unroll
    for (int k = 0; k < 16; ++k) acc[k] = __ldg(b2 + c * 16 + k);
#pragma unroll 4
    for (int j = 0; j < 64; ++j) {
        const float hj = sh1[nl][j];
        const float4* row = reinterpret_cast<const float4*>(sW2 + j * 64 + c * 16);
#pragma unroll
        for (int q = 0; q < 4; ++q) {
            const float4 w = row[q];
            acc[q * 4 + 0] = fmaf(hj, w.x, acc[q * 4 + 0]);
            acc[q * 4 + 1] = fmaf(hj, w.y, acc[q * 4 + 1]);
            acc[q * 4 + 2] = fmaf(hj, w.z, acc[q * 4 + 2]);
            acc[q * 4 + 3] = fmaf(hj, w.w, acc[q * 4 + 3]);
        }
    }
    float part = 0.0f;
#pragma unroll
    for (int k = 0; k < 16; ++k)
        part = fmaf(fmaxf(acc[k], 0.0f), __ldg(W3 + c * 16 + k), part);
    part += __shfl_down_sync(0xFFFFFFFFu, part, 2);
    part += __shfl_down_sync(0xFFFFFFFFu, part, 1);
    if (c == 0 && node < NNODES) g_nodes[node] = part + __ldg(b3);
}

// ---------------------------------------------------------------------------
// simulate: 64 threads/CTA. Warp 0 computes; warp 1 drains double-buffered
// swizzled SMEM tiles to GMEM fully coalesced (4 covered 128B lines / STG).
// Per-step chain (20 cyc): den -> jv = fma(den,-p,q) -> {rho,jd} -> rc -> max.
// Prep for step t+2 anchored ENTIRELY on previous-iteration state
// (dd = den_prev + 3*dif_prev), so it issues during the chain's RAW wait.
// Table address: idx bits folded into one IMAD (no AND/min); te pipe 2-stage.
// ---------------------------------------------------------------------------
#define TAB_BYTES  (NNODES * 8)                // 8208 (incl. 2 pad entries)
#define Q_OFF      TAB_BYTES
#define BUF_OFF    9344                        // 128-aligned, > Q_OFF+QLEN*4
#define BUF_ARR    4096                        // 32 rows * 128B
#define BUF_P      (3 * BUF_ARR)               // 12288
#define SMEM_TOTAL (BUF_OFF + 2 * BUF_P)       // 33920

extern __shared__ char smem_raw[];

__device__ __forceinline__ uint32_t smem_u32(const void* p) {
    uint32_t a;
    asm("{ .reg .u64 t; cvta.to.shared.u64 t, %1; cvt.u32.u64 %0, t; }"
        : "=r"(a) : "l"(p));
    return a;
}
__device__ __forceinline__ void sts128(uint32_t a, float x, float y, float z, float w) {
    asm volatile("st.shared.v4.f32 [%0], {%1, %2, %3, %4};"
                 :: "r"(a), "f"(x), "f"(y), "f"(z), "f"(w) : "memory");
}
__device__ __forceinline__ float4 lds128(uint32_t a) {
    float4 v;
    asm volatile("ld.shared.v4.f32 {%0, %1, %2, %3}, [%4];"
                 : "=f"(v.x), "=f"(v.y), "=f"(v.z), "=f"(v.w) : "r"(a));
    return v;
}
#define BAR_SYNC(id)   asm volatile("bar.sync %0, 64;"   :: "r"(id) : "memory")
#define BAR_ARRIVE(id) asm volatile("bar.arrive %0, 64;" :: "r"(id) : "memory")

// exact reference increment: (((0.14f*(0.1f*t))*0.125f)*0.1f)
__device__ __forceinline__ float q_inc(float tf) {
    return __fmul_rn(__fmul_rn(__fmul_rn(SIGMA_C, __fmul_rn(DT_C, tf)),
                               0.125f), DT_C);
}

__global__ void __launch_bounds__(64, 1)
simulate_kernel(const float* __restrict__ Cv, const float* __restrict__ Kp,
                const float* __restrict__ jminp, float* __restrict__ out) {
    const int tid  = threadIdx.x;
    const int lane = tid & 31;
    const int wid  = tid >> 5;
    const float MAGIC = 12582912.0f;    // 1.5 * 2^23, bits 0x4B400000

    float2* s_tab = reinterpret_cast<float2*>(smem_raw);
    float*  sQ    = reinterpret_cast<float*>(smem_raw + Q_OFF);

    // cooperative tab build from g_nodes: 16 entries/thread
    {
        const int k0 = tid * (TABN / 64);
        float nm = __ldg(g_nodes + k0);
        float nc = __ldg(g_nodes + k0 + 1);
#pragma unroll 8
        for (int k = k0; k < k0 + TABN / 64; ++k) {
            const float np = __ldg(g_nodes + k + 2);
            const float slope = 0.5f * (np - nm);
            s_tab[k] = make_float2(fmaf(-slope, (float)k, nc), slope * INVH_F);
            nm = nc; nc = np;
        }
        if (tid == 63) {              // pad entries (affine extension of seg 1023)
            s_tab[TABN]     = s_tab[TABN - 1];
            s_tab[TABN + 1] = s_tab[TABN - 1];
        }
    }
    __syncthreads();

    const uint32_t tab32 = smem_u32(s_tab);
    const uint32_t tabC  = tab32 - 0x5A000000u;   // bits(MAGIC+idx)*8 + tabC = &tab[idx]
    const uint32_t buf32 = smem_u32(smem_raw + BUF_OFF);
    const int e0 = blockIdx.x * 32;

    if (wid == 1) {
        // =================== writer warp (all coalesced) ===================
        BAR_ARRIVE(3);
        BAR_ARRIVE(4);

        float* oth0 = out + (size_t)e0 * NT_C;
        float* ore0 = oth0 + (size_t)B_C * NT_C;
        float* ocu0 = ore0 + (size_t)B_C * NT_C;
        float* oti0 = ocu0 + (size_t)B_C * NT_C;

        const int elw = lane >> 3;
        const int ch  = lane & 7;

        // frozen region [0, 112): closed form, coalesced
#pragma unroll
        for (int eg = 0; eg < 8; ++eg) {
            const int el = eg * 4 + elw;
            const size_t ro = (size_t)el * NT_C;
#pragma unroll
            for (int cc = 0; cc < 4; ++cc) {
                const int chunk = cc * 8 + ch;
                if (chunk < T_FROZEN / 4) {
                    const int t0 = chunk * 4;
                    const float tf = (float)t0;
                    float j0 = __fmul_rn(tf, 0.00175f);
                    if (t0 == 0) j0 = 1e-3f;
                    *reinterpret_cast<float4*>(oth0 + ro + t0) =
                        make_float4(0.f, 0.f, 0.f, 0.f);
                    *reinterpret_cast<float4*>(ore0 + ro + t0) =
                        make_float4(R0_C, R0_C, R0_C, R0_C);
                    *reinterpret_cast<float4*>(ocu0 + ro + t0) =
                        make_float4(j0,
                                    __fmul_rn(tf + 1.0f, 0.00175f),
                                    __fmul_rn(tf + 2.0f, 0.00175f),
                                    __fmul_rn(tf + 3.0f, 0.00175f));
                    *reinterpret_cast<float4*>(oti0 + ro + t0) =
                        make_float4(__fmul_rn(DT_C, tf),
                                    __fmul_rn(DT_C, tf + 1.0f),
                                    __fmul_rn(DT_C, tf + 2.0f),
                                    __fmul_rn(DT_C, tf + 3.0f));
                }
            }
        }

        for (int tile = 0; tile < NTILES_A; ++tile) {
            const int p = tile & 1;
            BAR_SYNC(1 + p);
            const uint32_t bp = buf32 + p * BUF_P;
            const int base = T_FROZEN + tile * TILE_S;
            const float tq0 = (float)(base + ch * 4);
            const float4 tv = make_float4(__fmul_rn(DT_C, tq0),
                                          __fmul_rn(DT_C, tq0 + 1.0f),
                                          __fmul_rn(DT_C, tq0 + 2.0f),
                                          __fmul_rn(DT_C, tq0 + 3.0f));
#pragma unroll
            for (int eg = 0; eg < 8; ++eg) {
                const int el = eg * 4 + elw;
                const uint32_t sa = bp + (uint32_t)el * 128u
                                  + (uint32_t)((ch ^ (el & 7)) << 4);
                const float4 a = lds128(sa + 0 * BUF_ARR);
                const float4 b = lds128(sa + 1 * BUF_ARR);
                const float4 c = lds128(sa + 2 * BUF_ARR);
                const size_t go = (size_t)el * NT_C + base + ch * 4;
                *reinterpret_cast<float4*>(oth0 + go) = a;
                *reinterpret_cast<float4*>(ore0 + go) = b;
                *reinterpret_cast<float4*>(ocu0 + go) = c;
                *reinterpret_cast<float4*>(oti0 + go) = tv;
            }
            BAR_ARRIVE(3 + p);
        }
        return;
    }

    // =================== compute warp ===================
    // exact serial Q prefix (all lanes redundantly; lane 0 stores)
    {
        float Q = 0.0f;
        if (lane == 0) sQ[0] = 0.0f;
        for (int t = 1; t < QLEN; t += 4) {
            const float f0 = (float)t;
            const float i0 = q_inc(f0);
            const float i1 = q_inc(f0 + 1.0f);
            const float i2 = q_inc(f0 + 2.0f);
            const float i3 = q_inc(f0 + 3.0f);
            Q = __fadd_rn(Q, i0); if (lane == 0) sQ[t]     = Q;
            Q = __fadd_rn(Q, i1); if (lane == 0) sQ[t + 1] = Q;
            Q = __fadd_rn(Q, i2); if (lane == 0) sQ[t + 2] = Q;
            Q = __fadd_rn(Q, i3); if (lane == 0) sQ[t + 3] = Q;
        }
    }
    __syncwarp();

    const int e = e0 + lane;
    const float cv  = __ldg(Cv + e);
    const float kk  = __ldg(Kp + e);
    const float jmn = __ldg(jminp + e);

    const double beta_d = 0.14 * 1.0 / (0.14 * 50.0 + 1.0);
    const float CQ = (float)pow(81.0 / (128.0 * beta_d), 1.0 / 3.0);
    const float Qmin = CQ * powf(kk, 4.0f / 3.0f);     // in [1.31, 5.69)

    // t* = first t with Q_t > Qmin  (t* in [113, 257))
    int lo = 0, hi = QLEN;
    while (hi - lo > 1) {
        const int mid = (lo + hi) >> 1;
        if (sQ[mid] <= Qmin) lo = mid; else hi = mid;
    }
    const int tstar = hi;
    const int tmax  = __reduce_max_sync(0xFFFFFFFFu, tstar);

    int steadyTile = (tmax + 2 - T_FROZEN + TILE_S - 1) / TILE_S;
    if (steadyTile > NTILES_A) steadyTile = NTILES_A;

    float res = R0_C, thk = 0.0f;
    const float cvdt = __fmul_rn(cv, DT_C);
    const float mjcC = __fmul_rn(-jmn, cvdt);

    // pipeline init at t0 = 112 (all lanes frozen through >= 113)
    float u = 0.125f;                                   // exact 1/8
    float den_prev = 8.0f, dif_prev = 0.0f;             // den_111, den_111-den_110
    const float nuA = __fmul_rn(__fmul_rn(112.0f, 0.014f), 0.125f);
    const float nuB = __fmul_rn(__fmul_rn(113.0f, 0.014f), 0.125f);
    float p0 = __fmul_rn(nuA, 0.125f), q0 = __fmul_rn(nuA, 2.0f);
    float p1 = __fmul_rn(nuB, 0.125f), q1 = __fmul_rn(nuB, 2.0f);
    float c00, c10, c01, c11;                           // te pipe: cur / next
#pragma unroll
    for (int k = 0; k < 2; ++k) {
        const float jk = __fmul_rn(112.0f + (float)k, 0.00175f);
        const float m  = fmaf(jk, INVH_F, MAGIC);
        uint32_t iu = __float_as_uint(m) & 0x3FFFFFu;
        iu = min(iu, (uint32_t)(TABN - 1));
        const float2 te = s_tab[iu];
        if (k == 0) { c00 = te.x; c10 = te.y; }
        else        { c01 = te.x; c11 = te.y; }
    }
    float cvde0 = 0.0f, mjc0 = 0.0f;                    // t=112 < t*
    float cvde1 = 0.0f, mjc1 = 0.0f;                    // t=113 < t*
    float tcp = 114.0f;                                 // t being prepped

    const uint32_t row_l = buf32 + (uint32_t)lane * 128u;
    const uint32_t sw_l  = (uint32_t)((lane & 7) << 4);
    float sth[4], sre[4], scu[4];

    int tile = 0;
    // -------- transition tiles (per-step gate) --------
    for (; tile < steadyTile; ++tile) {
        const int p = tile & 1;
        BAR_SYNC(3 + p);
        const uint32_t bp = row_l + p * BUF_P;
        const int base = T_FROZEN + tile * TILE_S;
#pragma unroll
        for (int s = 0; s < TILE_S; ++s) {
            // ---- prep step t+2: depends ONLY on prev-iteration state ----
            const float dd  = fmaf(dif_prev, 3.0f, den_prev);  // ~den_{t+2}
            const float tN  = fmaf(dd, -u, 2.0f);              // self-Newton
            const float u2  = __fmul_rn(u, tN);
            const float cu  = __fmul_rn(u2, 0.014f);
            const float nu2 = __fmul_rn(tcp, cu);              // predicted j_{t+2}
            const float p2  = __fmul_rn(nu2, u2);
            const float q2  = __fmul_rn(nu2, 2.0f);
            const float m   = fmaf(nu2, INVH_F, MAGIC);
            const uint32_t addr = __float_as_uint(m) * 8u + tabC;
            float na, nb;
            asm volatile("ld.shared.v2.f32 {%0, %1}, [%2];"
                         : "=f"(na), "=f"(nb) : "r"(addr));
            const bool a2 = (base + s + 2 >= tstar);
            const float cd2 = a2 ? cvdt : 0.0f;
            const float mj2 = a2 ? mjcC : 0.0f;
            u = u2; tcp += 1.0f;
            // ---------------- critical chain (20 cyc) ----------------
            const float resin = res;
            const float den = fmaf(resin, SIGMA_C, 1.0f);
            const float jv  = fmaf(den, -p0, q0);
            const float rho = fmaf(jv, c10, c00);
            const float jd  = fmaf(jv, cvde0, mjc0);           // frozen: exactly 0
            const float rc  = fmaf(rho, jd, resin);
            res = fmaxf(rc, R0_C);
            thk = fmaxf(thk + jd, 0.0f);
            sth[s & 3] = thk; sre[s & 3] = res; scu[s & 3] = jv;
            // ---------------- bookkeeping / rotate ----------------
            dif_prev = den - den_prev;
            den_prev = den;
            p0 = p1; q0 = q1; p1 = p2; q1 = q2;
            c00 = c01; c10 = c11; c01 = na; c11 = nb;
            cvde0 = cvde1; mjc0 = mjc1; cvde1 = cd2; mjc1 = mj2;
            if ((s & 3) == 3) {
                const uint32_t co = (uint32_t)(((s >> 2) << 4)) ^ sw_l;
                sts128(bp + 0 * BUF_ARR + co, sth[0], sth[1], sth[2], sth[3]);
                sts128(bp + 1 * BUF_ARR + co, sre[0], sre[1], sre[2], sre[3]);
                sts128(bp + 2 * BUF_ARR + co, scu[0], scu[1], scu[2], scu[3]);
            }
        }
        BAR_ARRIVE(1 + p);
    }
    // -------- steady tiles (gate constant) --------
    for (; tile < NTILES_A; ++tile) {
        const int p = tile & 1;
        BAR_SYNC(3 + p);
        const uint32_t bp = row_l + p * BUF_P;
#pragma unroll
        for (int s = 0; s < TILE_S; ++s) {
            // ---- prep step t+2 (independent of current chain) ----
            const float dd  = fmaf(dif_prev, 3.0f, den_prev);
            const float tN  = fmaf(dd, -u, 2.0f);
            const float u2  = __fmul_rn(u, tN);
            const float cu  = __fmul_rn(u2, 0.014f);
            const float nu2 = __fmul_rn(tcp, cu);
            const float p2  = __fmul_rn(nu2, u2);
            const float q2  = __fmul_rn(nu2, 2.0f);
            const float m   = fmaf(nu2, INVH_F, MAGIC);
            const uint32_t addr = __float_as_uint(m) * 8u + tabC;
            float na, nb;
            asm volatile("ld.shared.v2.f32 {%0, %1}, [%2];"
                         : "=f"(na), "=f"(nb) : "r"(addr));
            u = u2; tcp += 1.0f;
            // ---------------- critical chain ----------------
            const float resin = res;
            const float den = fmaf(resin, SIGMA_C, 1.0f);
            const float jv  = fmaf(den, -p0, q0);
            const float rho = fmaf(jv, c10, c00);
            const float jd  = fmaf(jv, cvdt, mjcC);
            const float rc  = fmaf(rho, jd, resin);
            res = fmaxf(rc, R0_C);
            thk = fmaxf(thk + jd, 0.0f);
            sth[s & 3] = thk; sre[s & 3] = res; scu[s & 3] = jv;
            // ---------------- bookkeeping / rotate ----------------
            dif_prev = den - den_prev;
            den_prev = den;
            p0 = p1; q0 = q1; p1 = p2; q1 = q2;
            c00 = c01; c10 = c11; c01 = na; c11 = nb;
            if ((s & 3) == 3) {
                const uint32_t co = (uint32_t)(((s >> 2) << 4)) ^ sw_l;
                sts128(bp + 0 * BUF_ARR + co, sth[0], sth[1], sth[2], sth[3]);
                sts128(bp + 1 * BUF_ARR + co, sre[0], sre[1], sre[2], sre[3]);
                sts128(bp + 2 * BUF_ARR + co, scu[0], scu[1], scu[2], scu[3]);
            }
        }
        BAR_ARRIVE(1 + p);
    }
}

// ---------------------------------------------------------------------------
// Inputs: Cv, K, jmin, W1, b1, W2, b2, W3, b3
// Output: concat(thickness, resistance, current, time), each (B, NT).
// ---------------------------------------------------------------------------
extern "C" void kernel_launch(void* const* d_in, const int* in_sizes, int n_in,
                              void* d_out, int out_size) {
    const float* Cv = (const float*)d_in[0];
    const float* K  = (const float*)d_in[1];
    const float* jm = (const float*)d_in[2];
    const float* W1 = (const float*)d_in[3];
    const float* b1 = (const float*)d_in[4];
    const float* W2 = (const float*)d_in[5];
    const float* b2 = (const float*)d_in[6];
    const float* W3 = (const float*)d_in[7];
    const float* b3 = (const float*)d_in[8];
    float* out = (float*)d_out;

    build_nodes_kernel<<<NODE_BLOCKS, 128>>>(W1, b1, W2, b2, W3, b3);

    cudaFuncSetAttribute(simulate_kernel,
                         cudaFuncAttributeMaxDynamicSharedMemorySize, SMEM_TOTAL);
    simulate_kernel<<<B_C / 32, 64, SMEM_TOTAL>>>(Cv, K, jm, out);
}